// round 5
// baseline (speedup 1.0000x reference)
#include <cuda_runtime.h>
#include <math.h>

#define BB 16
#define TT 1025
#define DD 1024
#define EE 8
#define RR 128
#define CC 192
#define N1 1536            // EE*CC
#define NTOK 16384         // BB*(TT-1)
#define NTOT (16*1025*1024)

// -------- scratch (static device arrays; no allocations) --------
__device__ float g_probs[NTOK * EE];                       // 512 KB
__device__ float g_mid[(size_t)NTOK * N1];                 // ~100.7 MB
__device__ float g_wdt[(size_t)DD * N1];                   // W_down^T: [k][n]
__device__ float g_wut[(size_t)N1 * DD];                   // W_up reshaped: [k=e*C+c][d]
__device__ double g_ortho;                                 // fp64 accumulator
__device__ double g_ent;                                   // fp64 accumulator

// ---------------- init: CLS copy + zero accumulators ----------------
__global__ void init_kernel(const float* __restrict__ x, float* __restrict__ out) {
    int i = blockIdx.x * blockDim.x + threadIdx.x;
    int nvec = BB * DD / 4;
    if (i < nvec) {
        int b = i / (DD / 4);
        int d4 = i % (DD / 4);
        size_t off = (size_t)b * TT * DD + d4 * 4;   // token t=0
        *(float4*)(out + off) = *(const float4*)(x + off);
    } else if (i == nvec) {
        g_ortho = 0.0;
    } else if (i == nvec + 1) {
        g_ent = 0.0;
    }
}

// ---------------- finalize: write scalars ----------------
__global__ void finalize_kernel(float* __restrict__ out) {
    if (threadIdx.x == 0) {
        out[NTOT]     = (float)(0.001 * g_ortho);
        out[NTOT + 1] = (float)(g_ent * (1.0 / (double)NTOK));
    }
}

// ---------------- weight transposes ----------------
__global__ void transpose_w(const float* __restrict__ Wd, const float* __restrict__ Wu) {
    for (int i = blockIdx.x * blockDim.x + threadIdx.x; i < N1 * DD;
         i += gridDim.x * blockDim.x) {
        // Wd: [n=e*C+c][d] row-major  ->  g_wdt[k=d][n]
        int n = i / DD, k = i % DD;
        g_wdt[(size_t)k * N1 + n] = Wd[i];
        // Wu: [(e*D+d)*C + c]  ->  g_wut[k=e*C+c][d]
        int c = i % CC;
        int ed = i / CC;
        int d2 = ed % DD;
        int e2 = ed / DD;
        g_wut[(size_t)(e2 * CC + c) * DD + d2] = Wu[i];
    }
}

// ---------------- ortho penalty ----------------
// Gram entries computed in fp32 emulating cublas splitK=2 (two contiguous
// ascending-k FMA chains of 512, partials added in fp32), then the residual
// square-sum in fp64. This replicates the reference's fp32 rounding pattern,
// which dominates the value of this ill-conditioned scalar.
// grid.x = 256: blocks 0..127 -> Q column i, 128..255 -> P column i
__global__ void ortho_kernel(const float* __restrict__ Q, const float* __restrict__ P) {
    const float* M = (blockIdx.x < RR) ? Q : P;
    int i = blockIdx.x & (RR - 1);
    __shared__ float col[DD];
    __shared__ double red[RR];
    for (int d = threadIdx.x; d < DD; d += RR) col[d] = M[(size_t)d * RR + i];
    __syncthreads();
    int j = threadIdx.x;
    float s1 = 0.0f, s2 = 0.0f;
    for (int d = 0; d < DD / 2; d++)
        s1 = fmaf(col[d], M[(size_t)d * RR + j], s1);
    for (int d = DD / 2; d < DD; d++)
        s2 = fmaf(col[d], M[(size_t)d * RR + j], s2);
    float G = s1 + s2;
    double r = (double)G - (j == i ? 1.0 : 0.0);
    red[j] = r * r;
    __syncthreads();
    for (int st = RR / 2; st > 0; st >>= 1) {
        if (j < st) red[j] += red[j + st];
        __syncthreads();
    }
    if (j == 0) atomicAdd(&g_ortho, red[0]);
}

// ---------------- router: z = h@Q, e, logits, probs, entropy ----------------
__global__ __launch_bounds__(256) void router_kernel(
    const float* __restrict__ x, const float* __restrict__ Q,
    const float* __restrict__ gamma, const float* __restrict__ masks,
    const float* __restrict__ bias) {
    __shared__ float gm[EE][RR + 1];       // gamma[r]*softmax_e(masks)[e][r]
    __shared__ float hs[32][32];
    __shared__ float Qs[32][RR];
    __shared__ float zsq[32][RR + 1];
    __shared__ float lg[32][EE];
    __shared__ float ent[32];
    __shared__ float sinv[32];
    __shared__ size_t rowoff[32];

    int tid = threadIdx.x;
    if (tid < RR) {
        float mv[EE];
        float mx = -1e30f;
        #pragma unroll
        for (int e = 0; e < EE; e++) { mv[e] = masks[e * RR + tid]; mx = fmaxf(mx, mv[e]); }
        float ss = 0.0f;
        #pragma unroll
        for (int e = 0; e < EE; e++) { mv[e] = expf(mv[e] - mx); ss += mv[e]; }
        float g = gamma[tid] / ss;
        #pragma unroll
        for (int e = 0; e < EE; e++) gm[e][tid] = mv[e] * g;
    }
    int tok0 = blockIdx.x * 32;
    if (tid < 32) {
        int gi = tok0 + tid;
        int b = gi >> 10;
        int t = (gi & 1023) + 1;
        rowoff[tid] = ((size_t)b * TT + t) * DD;
    }
    __syncthreads();

    int tok = tid >> 3, rs = tid & 7;   // thread owns z[tok][rs + 8j], j<16
    float acc[16];
    #pragma unroll
    for (int j = 0; j < 16; j++) acc[j] = 0.0f;

    for (int kb = 0; kb < DD; kb += 32) {
        #pragma unroll
        for (int l = 0; l < 4; l++) {
            int lin = tid + 256 * l;
            int tk = lin >> 5, kk = lin & 31;
            hs[tk][kk] = x[rowoff[tk] + kb + kk];
        }
        #pragma unroll
        for (int l = 0; l < 16; l++) {
            int lin = tid + 256 * l;
            int kk = lin >> 7, rr2 = lin & 127;
            Qs[kk][rr2] = Q[(size_t)(kb + kk) * RR + rr2];
        }
        __syncthreads();
        #pragma unroll
        for (int kk = 0; kk < 32; kk++) {
            float a = hs[tok][kk];
            #pragma unroll
            for (int j = 0; j < 16; j++) acc[j] = fmaf(a, Qs[kk][j * 8 + rs], acc[j]);
        }
        __syncthreads();
    }
    #pragma unroll
    for (int j = 0; j < 16; j++) zsq[tok][j * 8 + rs] = acc[j] * acc[j];
    __syncthreads();

    if (tid < 32) {
        float s = 0.0f;
        #pragma unroll 8
        for (int r = 0; r < RR; r++) s += zsq[tid][r];
        sinv[tid] = 1.0f / (s + 1e-6f);
    }
    __syncthreads();
    {
        int tk = tid >> 3, e = tid & 7;
        float s = 0.0f;
        #pragma unroll 8
        for (int r = 0; r < RR; r++) s = fmaf(zsq[tk][r], gm[e][r], s);
        lg[tk][e] = s * sinv[tk] + bias[e];
    }
    __syncthreads();
    if (tid < 32) {
        float mx = -1e30f;
        #pragma unroll
        for (int e = 0; e < EE; e++) mx = fmaxf(mx, lg[tid][e]);
        float ss = 0.0f;
        float p[EE];
        #pragma unroll
        for (int e = 0; e < EE; e++) { p[e] = expf(lg[tid][e] - mx); ss += p[e]; }
        float inv = 1.0f / ss;
        float hent = 0.0f;
        #pragma unroll
        for (int e = 0; e < EE; e++) {
            p[e] *= inv;
            hent -= p[e] * logf(fmaxf(p[e], 1e-9f));
            g_probs[(size_t)(tok0 + tid) * EE + e] = p[e];
        }
        ent[tid] = hent;
    }
    __syncthreads();
    if (tid == 0) {
        double s = 0.0;
        for (int i2 = 0; i2 < 32; i2++) s += (double)ent[i2];
        atomicAdd(&g_ent, s);
    }
}

// ---------------- down GEMM: mid = gelu(h @ Wd^T) * probs ----------------
// M=NTOK, N=N1, K=DD.  A = h rows (per-token ptr), B = g_wdt [k][n]
__global__ __launch_bounds__(256) void down_kernel(const float* __restrict__ x) {
    __shared__ float As[16][128];
    __shared__ float Bs[16][128];
    __shared__ size_t rowoff[128];
    int tid = threadIdx.x;
    int mb = blockIdx.y, nb = blockIdx.x;
    if (tid < 128) {
        int gi = mb * 128 + tid;
        int b = gi >> 10;
        int t = (gi & 1023) + 1;
        rowoff[tid] = ((size_t)b * TT + t) * DD;
    }
    __syncthreads();
    float acc[8][8];
    #pragma unroll
    for (int i = 0; i < 8; i++)
        #pragma unroll
        for (int j = 0; j < 8; j++) acc[i][j] = 0.0f;
    int tx = tid & 15, ty = tid >> 4;

    for (int kb = 0; kb < DD; kb += 16) {
        #pragma unroll
        for (int l = 0; l < 2; l++) {
            int lin4 = tid + 256 * l;
            int row = lin4 >> 2, kq = (lin4 & 3) * 4;
            float4 v = *(const float4*)(x + rowoff[row] + kb + kq);
            As[kq][row] = v.x; As[kq + 1][row] = v.y;
            As[kq + 2][row] = v.z; As[kq + 3][row] = v.w;
        }
        #pragma unroll
        for (int l = 0; l < 2; l++) {
            int lin4 = tid + 256 * l;
            int kk = lin4 >> 5, nn = (lin4 & 31) * 4;
            *(float4*)&Bs[kk][nn] =
                *(const float4*)(g_wdt + (size_t)(kb + kk) * N1 + nb * 128 + nn);
        }
        __syncthreads();
        #pragma unroll
        for (int kk = 0; kk < 16; kk++) {
            float a[8], b[8];
            *(float4*)&a[0] = *(float4*)&As[kk][ty * 8];
            *(float4*)&a[4] = *(float4*)&As[kk][ty * 8 + 4];
            *(float4*)&b[0] = *(float4*)&Bs[kk][tx * 8];
            *(float4*)&b[4] = *(float4*)&Bs[kk][tx * 8 + 4];
            #pragma unroll
            for (int i = 0; i < 8; i++)
                #pragma unroll
                for (int j = 0; j < 8; j++) acc[i][j] = fmaf(a[i], b[j], acc[i][j]);
        }
        __syncthreads();
    }
    int n0 = nb * 128 + tx * 8;
    int e = n0 / CC;                 // 8-wide block never straddles an expert
    #pragma unroll
    for (int i = 0; i < 8; i++) {
        int gmrow = mb * 128 + ty * 8 + i;
        float p = g_probs[(size_t)gmrow * EE + e];
        float vv[8];
        #pragma unroll
        for (int j = 0; j < 8; j++) {
            float v = acc[i][j];
            float gl = 0.5f * v * (1.0f + erff(v * 0.70710678118654752f));
            vv[j] = gl * p;
        }
        float* dst = g_mid + (size_t)gmrow * N1 + n0;
        *(float4*)(dst) = make_float4(vv[0], vv[1], vv[2], vv[3]);
        *(float4*)(dst + 4) = make_float4(vv[4], vv[5], vv[6], vv[7]);
    }
}

// ---------------- up GEMM: y = h + alpha * (mid @ Wu') ----------------
// M=NTOK, N=DD, K=N1.  A = g_mid, B = g_wut [k][d]
__global__ __launch_bounds__(256) void up_kernel(const float* __restrict__ x,
                                                 const float* __restrict__ alphap,
                                                 float* __restrict__ out) {
    __shared__ float As[16][128];
    __shared__ float Bs[16][128];
    int tid = threadIdx.x;
    int mb = blockIdx.y, nb = blockIdx.x;
    float acc[8][8];
    #pragma unroll
    for (int i = 0; i < 8; i++)
        #pragma unroll
        for (int j = 0; j < 8; j++) acc[i][j] = 0.0f;
    int tx = tid & 15, ty = tid >> 4;

    for (int kb = 0; kb < N1; kb += 16) {
        #pragma unroll
        for (int l = 0; l < 2; l++) {
            int lin4 = tid + 256 * l;
            int row = lin4 >> 2, kq = (lin4 & 3) * 4;
            float4 v = *(const float4*)(g_mid + (size_t)(mb * 128 + row) * N1 + kb + kq);
            As[kq][row] = v.x; As[kq + 1][row] = v.y;
            As[kq + 2][row] = v.z; As[kq + 3][row] = v.w;
        }
        #pragma unroll
        for (int l = 0; l < 2; l++) {
            int lin4 = tid + 256 * l;
            int kk = lin4 >> 5, nn = (lin4 & 31) * 4;
            *(float4*)&Bs[kk][nn] =
                *(const float4*)(g_wut + (size_t)(kb + kk) * DD + nb * 128 + nn);
        }
        __syncthreads();
        #pragma unroll
        for (int kk = 0; kk < 16; kk++) {
            float a[8], b[8];
            *(float4*)&a[0] = *(float4*)&As[kk][ty * 8];
            *(float4*)&a[4] = *(float4*)&As[kk][ty * 8 + 4];
            *(float4*)&b[0] = *(float4*)&Bs[kk][tx * 8];
            *(float4*)&b[4] = *(float4*)&Bs[kk][tx * 8 + 4];
            #pragma unroll
            for (int i = 0; i < 8; i++)
                #pragma unroll
                for (int j = 0; j < 8; j++) acc[i][j] = fmaf(a[i], b[j], acc[i][j]);
        }
        __syncthreads();
    }
    float alpha = *alphap;
    #pragma unroll
    for (int i = 0; i < 8; i++) {
        int gi = mb * 128 + ty * 8 + i;
        int b = gi >> 10;
        int t = (gi & 1023) + 1;
        size_t ro = ((size_t)b * TT + t) * DD + nb * 128 + tx * 8;
        float4 h1 = *(const float4*)(x + ro);
        float4 h2 = *(const float4*)(x + ro + 4);
        float4 o1, o2;
        o1.x = fmaf(alpha, acc[i][0], h1.x);
        o1.y = fmaf(alpha, acc[i][1], h1.y);
        o1.z = fmaf(alpha, acc[i][2], h1.z);
        o1.w = fmaf(alpha, acc[i][3], h1.w);
        o2.x = fmaf(alpha, acc[i][4], h2.x);
        o2.y = fmaf(alpha, acc[i][5], h2.y);
        o2.z = fmaf(alpha, acc[i][6], h2.z);
        o2.w = fmaf(alpha, acc[i][7], h2.w);
        *(float4*)(out + ro) = o1;
        *(float4*)(out + ro + 4) = o2;
    }
}

// ---------------- launch ----------------
extern "C" void kernel_launch(void* const* d_in, const int* in_sizes, int n_in,
                              void* d_out, int out_size) {
    const float* x     = (const float*)d_in[0];
    const float* Q     = (const float*)d_in[1];
    const float* P     = (const float*)d_in[2];
    const float* gamma = (const float*)d_in[3];
    const float* masks = (const float*)d_in[4];
    const float* bias  = (const float*)d_in[5];
    const float* Wd    = (const float*)d_in[6];
    const float* Wu    = (const float*)d_in[7];
    const float* alpha = (const float*)d_in[8];
    float* out = (float*)d_out;

    init_kernel<<<(BB * DD / 4 + 2 + 255) / 256, 256>>>(x, out);
    transpose_w<<<2048, 256>>>(Wd, Wu);
    ortho_kernel<<<2 * RR, RR>>>(Q, P);
    router_kernel<<<NTOK / 32, 256>>>(x, Q, gamma, masks, bias);
    down_kernel<<<dim3(N1 / 128, NTOK / 128), 256>>>(x);
    up_kernel<<<dim3(DD / 128, NTOK / 128), 256>>>(x, alpha, out);
    finalize_kernel<<<1, 32>>>(out);
}

// round 6
// speedup vs baseline: 1.7943x; 1.7943x over previous
#include <cuda_runtime.h>
#include <math.h>
#include <stdint.h>

#define BB 16
#define TT 1025
#define DD 1024
#define EE 8
#define RR 128
#define CC 192
#define N1 1536            // EE*CC
#define NTOK 16384         // BB*(TT-1)
#define NTOT (16*1025*1024)

// -------- scratch (static device arrays; no allocations) --------
__device__ float g_probs[NTOK * EE];                       // 512 KB
__device__ float g_mid[(size_t)NTOK * N1];                 // ~100.7 MB
__device__ float g_wdt[(size_t)DD * N1];                   // W_down^T: [k][n]
__device__ float g_wut[(size_t)N1 * DD];                   // W_up reshaped: [k=e*C+c][d]
__device__ double g_ortho;                                 // fp64 accumulator
__device__ double g_ent;                                   // fp64 accumulator

// -------- tf32 mma helpers --------
__device__ __forceinline__ uint32_t f2tf32(float f) {
    uint32_t u;
    asm("cvt.rna.tf32.f32 %0, %1;" : "=r"(u) : "f"(f));
    return u;
}
__device__ __forceinline__ void mma_tf32(float* c,
                                         uint32_t a0, uint32_t a1, uint32_t a2, uint32_t a3,
                                         uint32_t b0, uint32_t b1) {
    asm volatile("mma.sync.aligned.m16n8k8.row.col.f32.tf32.tf32.f32 "
                 "{%0,%1,%2,%3}, {%4,%5,%6,%7}, {%8,%9}, {%0,%1,%2,%3};"
                 : "+f"(c[0]), "+f"(c[1]), "+f"(c[2]), "+f"(c[3])
                 : "r"(a0), "r"(a1), "r"(a2), "r"(a3), "r"(b0), "r"(b1));
}

// ---------------- init: CLS copy + zero accumulators ----------------
__global__ void init_kernel(const float* __restrict__ x, float* __restrict__ out) {
    int i = blockIdx.x * blockDim.x + threadIdx.x;
    int nvec = BB * DD / 4;
    if (i < nvec) {
        int b = i / (DD / 4);
        int d4 = i % (DD / 4);
        size_t off = (size_t)b * TT * DD + d4 * 4;   // token t=0
        *(float4*)(out + off) = *(const float4*)(x + off);
    } else if (i == nvec) {
        g_ortho = 0.0;
    } else if (i == nvec + 1) {
        g_ent = 0.0;
    }
}

// ---------------- finalize: write scalars ----------------
__global__ void finalize_kernel(float* __restrict__ out) {
    if (threadIdx.x == 0) {
        out[NTOT]     = (float)(0.001 * g_ortho);
        out[NTOT + 1] = (float)(g_ent * (1.0 / (double)NTOK));
    }
}

// ---------------- weight transposes ----------------
__global__ void transpose_w(const float* __restrict__ Wd, const float* __restrict__ Wu) {
    for (int i = blockIdx.x * blockDim.x + threadIdx.x; i < N1 * DD;
         i += gridDim.x * blockDim.x) {
        int n = i / DD, k = i % DD;
        g_wdt[(size_t)k * N1 + n] = Wd[i];
        int c = i % CC;
        int ed = i / CC;
        int d2 = ed % DD;
        int e2 = ed / DD;
        g_wut[(size_t)(e2 * CC + c) * DD + d2] = Wu[i];
    }
}

// ---------------- ortho penalty (splitK=2 fp32 emulation, fp64 sum) -------
__global__ void ortho_kernel(const float* __restrict__ Q, const float* __restrict__ P) {
    const float* M = (blockIdx.x < RR) ? Q : P;
    int i = blockIdx.x & (RR - 1);
    __shared__ float col[DD];
    __shared__ double red[RR];
    for (int d = threadIdx.x; d < DD; d += RR) col[d] = M[(size_t)d * RR + i];
    __syncthreads();
    int j = threadIdx.x;
    float s1 = 0.0f, s2 = 0.0f;
    for (int d = 0; d < DD / 2; d++)
        s1 = fmaf(col[d], M[(size_t)d * RR + j], s1);
    for (int d = DD / 2; d < DD; d++)
        s2 = fmaf(col[d], M[(size_t)d * RR + j], s2);
    float G = s1 + s2;
    double r = (double)G - (j == i ? 1.0 : 0.0);
    red[j] = r * r;
    __syncthreads();
    for (int st = RR / 2; st > 0; st >>= 1) {
        if (j < st) red[j] += red[j + st];
        __syncthreads();
    }
    if (j == 0) atomicAdd(&g_ortho, red[0]);
}

// ---------------- router: z = h@Q, e, logits, probs, entropy ----------------
__global__ __launch_bounds__(256) void router_kernel(
    const float* __restrict__ x, const float* __restrict__ Q,
    const float* __restrict__ gamma, const float* __restrict__ masks,
    const float* __restrict__ bias) {
    __shared__ float gm[EE][RR + 1];
    __shared__ float hs[32][32];
    __shared__ float Qs[32][RR];
    __shared__ float zsq[32][RR + 1];
    __shared__ float lg[32][EE];
    __shared__ float ent[32];
    __shared__ float sinv[32];
    __shared__ size_t rowoff[32];

    int tid = threadIdx.x;
    if (tid < RR) {
        float mv[EE];
        float mx = -1e30f;
        #pragma unroll
        for (int e = 0; e < EE; e++) { mv[e] = masks[e * RR + tid]; mx = fmaxf(mx, mv[e]); }
        float ss = 0.0f;
        #pragma unroll
        for (int e = 0; e < EE; e++) { mv[e] = expf(mv[e] - mx); ss += mv[e]; }
        float g = gamma[tid] / ss;
        #pragma unroll
        for (int e = 0; e < EE; e++) gm[e][tid] = mv[e] * g;
    }
    int tok0 = blockIdx.x * 32;
    if (tid < 32) {
        int gi = tok0 + tid;
        int b = gi >> 10;
        int t = (gi & 1023) + 1;
        rowoff[tid] = ((size_t)b * TT + t) * DD;
    }
    __syncthreads();

    int tok = tid >> 3, rs = tid & 7;
    float acc[16];
    #pragma unroll
    for (int j = 0; j < 16; j++) acc[j] = 0.0f;

    for (int kb = 0; kb < DD; kb += 32) {
        #pragma unroll
        for (int l = 0; l < 4; l++) {
            int lin = tid + 256 * l;
            int tk = lin >> 5, kk = lin & 31;
            hs[tk][kk] = x[rowoff[tk] + kb + kk];
        }
        #pragma unroll
        for (int l = 0; l < 16; l++) {
            int lin = tid + 256 * l;
            int kk = lin >> 7, rr2 = lin & 127;
            Qs[kk][rr2] = Q[(size_t)(kb + kk) * RR + rr2];
        }
        __syncthreads();
        #pragma unroll
        for (int kk = 0; kk < 32; kk++) {
            float a = hs[tok][kk];
            #pragma unroll
            for (int j = 0; j < 16; j++) acc[j] = fmaf(a, Qs[kk][j * 8 + rs], acc[j]);
        }
        __syncthreads();
    }
    #pragma unroll
    for (int j = 0; j < 16; j++) zsq[tok][j * 8 + rs] = acc[j] * acc[j];
    __syncthreads();

    if (tid < 32) {
        float s = 0.0f;
        #pragma unroll 8
        for (int r = 0; r < RR; r++) s += zsq[tid][r];
        sinv[tid] = 1.0f / (s + 1e-6f);
    }
    __syncthreads();
    {
        int tk = tid >> 3, e = tid & 7;
        float s = 0.0f;
        #pragma unroll 8
        for (int r = 0; r < RR; r++) s = fmaf(zsq[tk][r], gm[e][r], s);
        lg[tk][e] = s * sinv[tk] + bias[e];
    }
    __syncthreads();
    if (tid < 32) {
        float mx = -1e30f;
        #pragma unroll
        for (int e = 0; e < EE; e++) mx = fmaxf(mx, lg[tid][e]);
        float ss = 0.0f;
        float p[EE];
        #pragma unroll
        for (int e = 0; e < EE; e++) { p[e] = expf(lg[tid][e] - mx); ss += p[e]; }
        float inv = 1.0f / ss;
        float hent = 0.0f;
        #pragma unroll
        for (int e = 0; e < EE; e++) {
            p[e] *= inv;
            hent -= p[e] * logf(fmaxf(p[e], 1e-9f));
            g_probs[(size_t)(tok0 + tid) * EE + e] = p[e];
        }
        ent[tid] = hent;
    }
    __syncthreads();
    if (tid == 0) {
        double s = 0.0;
        for (int i2 = 0; i2 < 32; i2++) s += (double)ent[i2];
        atomicAdd(&g_ent, s);
    }
}

// ---------------- down GEMM (tf32 tensor cores) ----------------
// mid = gelu(h @ Wd^T) * probs.  M=NTOK, N=N1, K=DD.
__global__ __launch_bounds__(256, 2) void down_kernel(const float* __restrict__ x) {
    __shared__ float As[16][136];
    __shared__ float Bs[16][136];
    __shared__ float sh_probs[128][EE];
    __shared__ size_t rowoff[128];
    int tid = threadIdx.x;
    int lane = tid & 31, wid = tid >> 5;
    int wm = wid & 1, wn = wid >> 1;          // warp tile: 64x32 at (wm*64, wn*32)
    int g = lane >> 2, t = lane & 3;
    int mb = blockIdx.y, nb = blockIdx.x;

    if (tid < 128) {
        int gi = mb * 128 + tid;
        int b = gi >> 10;
        int tt = (gi & 1023) + 1;
        rowoff[tid] = ((size_t)b * TT + tt) * DD;
    }
    {
        int r = tid >> 1, c4 = (tid & 1) * 4;
        *(float4*)&sh_probs[r][c4] =
            *(const float4*)(g_probs + (size_t)(mb * 128 + r) * EE + c4);
    }
    __syncthreads();

    float acc[16][4];
    #pragma unroll
    for (int i = 0; i < 16; i++)
        #pragma unroll
        for (int j = 0; j < 4; j++) acc[i][j] = 0.0f;

    for (int kb = 0; kb < DD; kb += 16) {
        #pragma unroll
        for (int l = 0; l < 2; l++) {
            int lin4 = tid + 256 * l;
            int row = lin4 >> 2, kq = (lin4 & 3) * 4;
            float4 v = *(const float4*)(x + rowoff[row] + kb + kq);
            As[kq][row] = v.x; As[kq + 1][row] = v.y;
            As[kq + 2][row] = v.z; As[kq + 3][row] = v.w;
        }
        #pragma unroll
        for (int l = 0; l < 2; l++) {
            int lin4 = tid + 256 * l;
            int kk = lin4 >> 5, nn = (lin4 & 31) * 4;
            *(float4*)&Bs[kk][nn] =
                *(const float4*)(g_wdt + (size_t)(kb + kk) * N1 + nb * 128 + nn);
        }
        __syncthreads();
        #pragma unroll
        for (int ks = 0; ks < 2; ks++) {
            int k0 = ks * 8;
            uint32_t bf[4][2];
            #pragma unroll
            for (int nf = 0; nf < 4; nf++) {
                int n0 = wn * 32 + nf * 8;
                bf[nf][0] = f2tf32(Bs[k0 + t][n0 + g]);
                bf[nf][1] = f2tf32(Bs[k0 + 4 + t][n0 + g]);
            }
            #pragma unroll
            for (int mf = 0; mf < 4; mf++) {
                int m0 = wm * 64 + mf * 16;
                uint32_t a0 = f2tf32(As[k0 + t][m0 + g]);
                uint32_t a1 = f2tf32(As[k0 + t][m0 + g + 8]);
                uint32_t a2 = f2tf32(As[k0 + 4 + t][m0 + g]);
                uint32_t a3 = f2tf32(As[k0 + 4 + t][m0 + g + 8]);
                #pragma unroll
                for (int nf = 0; nf < 4; nf++)
                    mma_tf32(acc[mf * 4 + nf], a0, a1, a2, a3, bf[nf][0], bf[nf][1]);
            }
        }
        __syncthreads();
    }
    // epilogue: gelu * probs -> g_mid
    #pragma unroll
    for (int mf = 0; mf < 4; mf++) {
        #pragma unroll
        for (int nf = 0; nf < 4; nf++) {
            float* c = acc[mf * 4 + nf];
            int cl = wn * 32 + nf * 8 + 2 * t;
            int ncol = nb * 128 + cl;
            int e = ncol / CC;
            #pragma unroll
            for (int h = 0; h < 2; h++) {
                int r = wm * 64 + mf * 16 + g + h * 8;
                float p = sh_probs[r][e];
                float v0 = c[h * 2], v1 = c[h * 2 + 1];
                float g0 = 0.5f * v0 * (1.0f + erff(v0 * 0.70710678118654752f)) * p;
                float g1 = 0.5f * v1 * (1.0f + erff(v1 * 0.70710678118654752f)) * p;
                *(float2*)(g_mid + (size_t)(mb * 128 + r) * N1 + ncol) =
                    make_float2(g0, g1);
            }
        }
    }
}

// ---------------- up GEMM (tf32 tensor cores) ----------------
// y = h + alpha * (mid @ Wu').  M=NTOK, N=DD, K=N1.
__global__ __launch_bounds__(256, 2) void up_kernel(const float* __restrict__ x,
                                                    const float* __restrict__ alphap,
                                                    float* __restrict__ out) {
    __shared__ float As[16][136];
    __shared__ float Bs[16][136];
    int tid = threadIdx.x;
    int lane = tid & 31, wid = tid >> 5;
    int wm = wid & 1, wn = wid >> 1;
    int g = lane >> 2, t = lane & 3;
    int mb = blockIdx.y, nb = blockIdx.x;

    float acc[16][4];
    #pragma unroll
    for (int i = 0; i < 16; i++)
        #pragma unroll
        for (int j = 0; j < 4; j++) acc[i][j] = 0.0f;

    for (int kb = 0; kb < N1; kb += 16) {
        #pragma unroll
        for (int l = 0; l < 2; l++) {
            int lin4 = tid + 256 * l;
            int row = lin4 >> 2, kq = (lin4 & 3) * 4;
            float4 v = *(const float4*)(g_mid + (size_t)(mb * 128 + row) * N1 + kb + kq);
            As[kq][row] = v.x; As[kq + 1][row] = v.y;
            As[kq + 2][row] = v.z; As[kq + 3][row] = v.w;
        }
        #pragma unroll
        for (int l = 0; l < 2; l++) {
            int lin4 = tid + 256 * l;
            int kk = lin4 >> 5, nn = (lin4 & 31) * 4;
            *(float4*)&Bs[kk][nn] =
                *(const float4*)(g_wut + (size_t)(kb + kk) * DD + nb * 128 + nn);
        }
        __syncthreads();
        #pragma unroll
        for (int ks = 0; ks < 2; ks++) {
            int k0 = ks * 8;
            uint32_t bf[4][2];
            #pragma unroll
            for (int nf = 0; nf < 4; nf++) {
                int n0 = wn * 32 + nf * 8;
                bf[nf][0] = f2tf32(Bs[k0 + t][n0 + g]);
                bf[nf][1] = f2tf32(Bs[k0 + 4 + t][n0 + g]);
            }
            #pragma unroll
            for (int mf = 0; mf < 4; mf++) {
                int m0 = wm * 64 + mf * 16;
                uint32_t a0 = f2tf32(As[k0 + t][m0 + g]);
                uint32_t a1 = f2tf32(As[k0 + t][m0 + g + 8]);
                uint32_t a2 = f2tf32(As[k0 + 4 + t][m0 + g]);
                uint32_t a3 = f2tf32(As[k0 + 4 + t][m0 + g + 8]);
                #pragma unroll
                for (int nf = 0; nf < 4; nf++)
                    mma_tf32(acc[mf * 4 + nf], a0, a1, a2, a3, bf[nf][0], bf[nf][1]);
            }
        }
        __syncthreads();
    }
    float alpha = *alphap;
    #pragma unroll
    for (int mf = 0; mf < 4; mf++) {
        #pragma unroll
        for (int nf = 0; nf < 4; nf++) {
            float* c = acc[mf * 4 + nf];
            int cl = wn * 32 + nf * 8 + 2 * t;
            int ncol = nb * 128 + cl;
            #pragma unroll
            for (int h = 0; h < 2; h++) {
                int r = wm * 64 + mf * 16 + g + h * 8;
                int gi = mb * 128 + r;
                int b = gi >> 10;
                int tt = (gi & 1023) + 1;
                size_t ro = ((size_t)b * TT + tt) * DD + ncol;
                float2 hx = *(const float2*)(x + ro);
                *(float2*)(out + ro) = make_float2(fmaf(alpha, c[h * 2], hx.x),
                                                   fmaf(alpha, c[h * 2 + 1], hx.y));
            }
        }
    }
}

// ---------------- launch ----------------
extern "C" void kernel_launch(void* const* d_in, const int* in_sizes, int n_in,
                              void* d_out, int out_size) {
    const float* x     = (const float*)d_in[0];
    const float* Q     = (const float*)d_in[1];
    const float* P     = (const float*)d_in[2];
    const float* gamma = (const float*)d_in[3];
    const float* masks = (const float*)d_in[4];
    const float* bias  = (const float*)d_in[5];
    const float* Wd    = (const float*)d_in[6];
    const float* Wu    = (const float*)d_in[7];
    const float* alpha = (const float*)d_in[8];
    float* out = (float*)d_out;

    init_kernel<<<(BB * DD / 4 + 2 + 255) / 256, 256>>>(x, out);
    transpose_w<<<2048, 256>>>(Wd, Wu);
    ortho_kernel<<<2 * RR, RR>>>(Q, P);
    router_kernel<<<NTOK / 32, 256>>>(x, Q, gamma, masks, bias);
    down_kernel<<<dim3(N1 / 128, NTOK / 128), 256>>>(x);
    up_kernel<<<dim3(DD / 128, NTOK / 128), 256>>>(x, alpha, out);
    finalize_kernel<<<1, 32>>>(out);
}

// round 7
// speedup vs baseline: 2.4171x; 1.3471x over previous
#include <cuda_runtime.h>
#include <math.h>
#include <stdint.h>

#define BB 16
#define TT 1025
#define DD 1024
#define EE 8
#define RR 128
#define CC 192
#define N1 1536            // EE*CC
#define NTOK 16384         // BB*(TT-1)
#define NTOT (16*1025*1024)

// -------- scratch (static device arrays; no allocations) --------
__device__ float g_probs[NTOK * EE];                       // 512 KB
__device__ float g_mid[(size_t)NTOK * N1];                 // ~100.7 MB
__device__ float g_wdt[(size_t)DD * N1];                   // W_down^T: [k][n]
__device__ float g_wut[(size_t)N1 * DD];                   // W_up reshaped: [k=e*C+c][d]
__device__ double g_ortho;                                 // fp64 accumulator
__device__ double g_ent;                                   // fp64 accumulator

// -------- tf32 mma helpers --------
__device__ __forceinline__ uint32_t f2tf32(float f) {
    uint32_t u;
    asm("cvt.rna.tf32.f32 %0, %1;" : "=r"(u) : "f"(f));
    return u;
}
__device__ __forceinline__ void mma_tf32(float* c,
                                         uint32_t a0, uint32_t a1, uint32_t a2, uint32_t a3,
                                         uint32_t b0, uint32_t b1) {
    asm volatile("mma.sync.aligned.m16n8k8.row.col.f32.tf32.tf32.f32 "
                 "{%0,%1,%2,%3}, {%4,%5,%6,%7}, {%8,%9}, {%0,%1,%2,%3};"
                 : "+f"(c[0]), "+f"(c[1]), "+f"(c[2]), "+f"(c[3])
                 : "r"(a0), "r"(a1), "r"(a2), "r"(a3), "r"(b0), "r"(b1));
}

// ---------------- init: CLS copy + zero accumulators ----------------
__global__ void init_kernel(const float* __restrict__ x, float* __restrict__ out) {
    int i = blockIdx.x * blockDim.x + threadIdx.x;
    int nvec = BB * DD / 4;
    if (i < nvec) {
        int b = i / (DD / 4);
        int d4 = i % (DD / 4);
        size_t off = (size_t)b * TT * DD + d4 * 4;   // token t=0
        *(float4*)(out + off) = *(const float4*)(x + off);
    } else if (i == nvec) {
        g_ortho = 0.0;
    } else if (i == nvec + 1) {
        g_ent = 0.0;
    }
}

// ---------------- finalize: write scalars ----------------
__global__ void finalize_kernel(float* __restrict__ out) {
    if (threadIdx.x == 0) {
        out[NTOT]     = (float)(0.001 * g_ortho);
        out[NTOT + 1] = (float)(g_ent * (1.0 / (double)NTOK));
    }
}

// ---------------- weight transposes ----------------
__global__ void transpose_w(const float* __restrict__ Wd, const float* __restrict__ Wu) {
    for (int i = blockIdx.x * blockDim.x + threadIdx.x; i < N1 * DD;
         i += gridDim.x * blockDim.x) {
        int n = i / DD, k = i % DD;
        g_wdt[(size_t)k * N1 + n] = Wd[i];
        int c = i % CC;
        int ed = i / CC;
        int d2 = ed % DD;
        int e2 = ed / DD;
        g_wut[(size_t)(e2 * CC + c) * DD + d2] = Wu[i];
    }
}

// ---------------- ortho penalty (splitK=2 fp32 emulation, fp64 sum) -------
__global__ void ortho_kernel(const float* __restrict__ Q, const float* __restrict__ P) {
    const float* M = (blockIdx.x < RR) ? Q : P;
    int i = blockIdx.x & (RR - 1);
    __shared__ float col[DD];
    __shared__ double red[RR];
    for (int d = threadIdx.x; d < DD; d += RR) col[d] = M[(size_t)d * RR + i];
    __syncthreads();
    int j = threadIdx.x;
    float s1 = 0.0f, s2 = 0.0f;
    for (int d = 0; d < DD / 2; d++)
        s1 = fmaf(col[d], M[(size_t)d * RR + j], s1);
    for (int d = DD / 2; d < DD; d++)
        s2 = fmaf(col[d], M[(size_t)d * RR + j], s2);
    float G = s1 + s2;
    double r = (double)G - (j == i ? 1.0 : 0.0);
    red[j] = r * r;
    __syncthreads();
    for (int st = RR / 2; st > 0; st >>= 1) {
        if (j < st) red[j] += red[j + st];
        __syncthreads();
    }
    if (j == 0) atomicAdd(&g_ortho, red[0]);
}

// ---------------- router (tensor-core fused) ----------------
// One CTA = 128 tokens. z = h@Q via tf32 mma (128x128xK=1024), then in-block:
// e = z^2 / sum, logits = e @ (gamma*softmax(masks))^T + bias, softmax,
// entropy, probs -> g_probs.
// Dynamic smem layout: zs[128][129] floats (A/B staging aliased on top),
// then gmv[8][129].
#define RZS 129
__global__ __launch_bounds__(256) void router_kernel(
    const float* __restrict__ x, const float* __restrict__ Q,
    const float* __restrict__ gamma, const float* __restrict__ masks,
    const float* __restrict__ bias) {
    extern __shared__ float sdyn[];
    float* zs = sdyn;                         // 128*129 floats
    float* gmv = sdyn + 128 * RZS;            // 8*129 floats
    uint32_t* As = (uint32_t*)sdyn;           // [16][136] aliased over zs
    uint32_t* Bs = As + 16 * 136;             // [16][136]
    __shared__ size_t rowoff[128];
    __shared__ float entS[128];

    int tid = threadIdx.x;
    int lane = tid & 31, wid = tid >> 5;
    int wm = wid & 1, wn = wid >> 1;
    int g = lane >> 2, t = lane & 3;
    int mb = blockIdx.x;
    int tok0 = mb * 128;

    if (tid < 128) {
        int gi = tok0 + tid;
        int b = gi >> 10;
        int tt = (gi & 1023) + 1;
        rowoff[tid] = ((size_t)b * TT + tt) * DD;
        // gm: gamma[r] * softmax_e(masks)[e][r]
        float mv[EE];
        float mx = -1e30f;
        #pragma unroll
        for (int e = 0; e < EE; e++) { mv[e] = masks[e * RR + tid]; mx = fmaxf(mx, mv[e]); }
        float ss = 0.0f;
        #pragma unroll
        for (int e = 0; e < EE; e++) { mv[e] = expf(mv[e] - mx); ss += mv[e]; }
        float gsc = gamma[tid] / ss;
        #pragma unroll
        for (int e = 0; e < EE; e++) gmv[e * RZS + tid] = mv[e] * gsc;
    }
    __syncthreads();

    float acc[16][4];
    #pragma unroll
    for (int i = 0; i < 16; i++)
        #pragma unroll
        for (int j = 0; j < 4; j++) acc[i][j] = 0.0f;

    for (int kb = 0; kb < DD; kb += 16) {
        #pragma unroll
        for (int l = 0; l < 2; l++) {
            int lin4 = tid + 256 * l;
            int row = lin4 >> 2, kq = (lin4 & 3) * 4;
            float4 v = *(const float4*)(x + rowoff[row] + kb + kq);
            As[(kq) * 136 + row]     = f2tf32(v.x);
            As[(kq + 1) * 136 + row] = f2tf32(v.y);
            As[(kq + 2) * 136 + row] = f2tf32(v.z);
            As[(kq + 3) * 136 + row] = f2tf32(v.w);
        }
        #pragma unroll
        for (int l = 0; l < 2; l++) {
            int lin4 = tid + 256 * l;
            int kk = lin4 >> 5, nn = (lin4 & 31) * 4;
            float4 v = *(const float4*)(Q + (size_t)(kb + kk) * RR + nn);
            Bs[kk * 136 + nn]     = f2tf32(v.x);
            Bs[kk * 136 + nn + 1] = f2tf32(v.y);
            Bs[kk * 136 + nn + 2] = f2tf32(v.z);
            Bs[kk * 136 + nn + 3] = f2tf32(v.w);
        }
        __syncthreads();
        #pragma unroll
        for (int ks = 0; ks < 2; ks++) {
            int k0 = ks * 8;
            uint32_t bf[4][2];
            #pragma unroll
            for (int nf = 0; nf < 4; nf++) {
                int n0 = wn * 32 + nf * 8;
                bf[nf][0] = Bs[(k0 + t) * 136 + n0 + g];
                bf[nf][1] = Bs[(k0 + 4 + t) * 136 + n0 + g];
            }
            #pragma unroll
            for (int mf = 0; mf < 4; mf++) {
                int m0 = wm * 64 + mf * 16;
                uint32_t a0 = As[(k0 + t) * 136 + m0 + g];
                uint32_t a1 = As[(k0 + t) * 136 + m0 + g + 8];
                uint32_t a2 = As[(k0 + 4 + t) * 136 + m0 + g];
                uint32_t a3 = As[(k0 + 4 + t) * 136 + m0 + g + 8];
                #pragma unroll
                for (int nf = 0; nf < 4; nf++)
                    mma_tf32(acc[mf * 4 + nf], a0, a1, a2, a3, bf[nf][0], bf[nf][1]);
            }
        }
        __syncthreads();
    }
    // write z^2 (overwrites A/B staging; all mma complete per last sync)
    #pragma unroll
    for (int mf = 0; mf < 4; mf++) {
        #pragma unroll
        for (int nf = 0; nf < 4; nf++) {
            float* c = acc[mf * 4 + nf];
            int cl = wn * 32 + nf * 8 + 2 * t;
            #pragma unroll
            for (int h = 0; h < 2; h++) {
                int r = wm * 64 + mf * 16 + g + h * 8;
                zs[r * RZS + cl]     = c[h * 2] * c[h * 2];
                zs[r * RZS + cl + 1] = c[h * 2 + 1] * c[h * 2 + 1];
            }
        }
    }
    __syncthreads();

    if (tid < 128) {
        float s = 0.0f;
        float lg[EE];
        #pragma unroll
        for (int e = 0; e < EE; e++) lg[e] = 0.0f;
        #pragma unroll 4
        for (int r = 0; r < RR; r++) {
            float zq = zs[tid * RZS + r];
            s += zq;
            #pragma unroll
            for (int e = 0; e < EE; e++) lg[e] = fmaf(zq, gmv[e * RZS + r], lg[e]);
        }
        float sinv = 1.0f / (s + 1e-6f);
        float mx = -1e30f;
        #pragma unroll
        for (int e = 0; e < EE; e++) { lg[e] = lg[e] * sinv + bias[e]; mx = fmaxf(mx, lg[e]); }
        float ss = 0.0f;
        #pragma unroll
        for (int e = 0; e < EE; e++) { lg[e] = expf(lg[e] - mx); ss += lg[e]; }
        float inv = 1.0f / ss;
        float hent = 0.0f;
        #pragma unroll
        for (int e = 0; e < EE; e++) {
            float p = lg[e] * inv;
            hent -= p * logf(fmaxf(p, 1e-9f));
            g_probs[(size_t)(tok0 + tid) * EE + e] = p;
        }
        entS[tid] = hent;
    }
    __syncthreads();
    for (int st = 64; st > 0; st >>= 1) {
        if (tid < st && tid + st < 128) entS[tid] += entS[tid + st];
        __syncthreads();
    }
    if (tid == 0) atomicAdd(&g_ent, (double)entS[0]);
}

// ---------------- down GEMM (tf32 tensor cores, pre-converted tiles) -------
// mid = gelu(h @ Wd^T) * probs.  M=NTOK, N=N1, K=DD.
__global__ __launch_bounds__(256, 2) void down_kernel(const float* __restrict__ x) {
    __shared__ uint32_t As[16][136];
    __shared__ uint32_t Bs[16][136];
    __shared__ float sh_probs[128][EE];
    __shared__ size_t rowoff[128];
    int tid = threadIdx.x;
    int lane = tid & 31, wid = tid >> 5;
    int wm = wid & 1, wn = wid >> 1;
    int g = lane >> 2, t = lane & 3;
    int mb = blockIdx.y, nb = blockIdx.x;

    if (tid < 128) {
        int gi = mb * 128 + tid;
        int b = gi >> 10;
        int tt = (gi & 1023) + 1;
        rowoff[tid] = ((size_t)b * TT + tt) * DD;
    }
    {
        int r = tid >> 1, c4 = (tid & 1) * 4;
        *(float4*)&sh_probs[r][c4] =
            *(const float4*)(g_probs + (size_t)(mb * 128 + r) * EE + c4);
    }
    __syncthreads();

    float acc[16][4];
    #pragma unroll
    for (int i = 0; i < 16; i++)
        #pragma unroll
        for (int j = 0; j < 4; j++) acc[i][j] = 0.0f;

    for (int kb = 0; kb < DD; kb += 16) {
        #pragma unroll
        for (int l = 0; l < 2; l++) {
            int lin4 = tid + 256 * l;
            int row = lin4 >> 2, kq = (lin4 & 3) * 4;
            float4 v = *(const float4*)(x + rowoff[row] + kb + kq);
            As[kq][row]     = f2tf32(v.x);
            As[kq + 1][row] = f2tf32(v.y);
            As[kq + 2][row] = f2tf32(v.z);
            As[kq + 3][row] = f2tf32(v.w);
        }
        #pragma unroll
        for (int l = 0; l < 2; l++) {
            int lin4 = tid + 256 * l;
            int kk = lin4 >> 5, nn = (lin4 & 31) * 4;
            float4 v = *(const float4*)(g_wdt + (size_t)(kb + kk) * N1 + nb * 128 + nn);
            Bs[kk][nn]     = f2tf32(v.x);
            Bs[kk][nn + 1] = f2tf32(v.y);
            Bs[kk][nn + 2] = f2tf32(v.z);
            Bs[kk][nn + 3] = f2tf32(v.w);
        }
        __syncthreads();
        #pragma unroll
        for (int ks = 0; ks < 2; ks++) {
            int k0 = ks * 8;
            uint32_t bf[4][2];
            #pragma unroll
            for (int nf = 0; nf < 4; nf++) {
                int n0 = wn * 32 + nf * 8;
                bf[nf][0] = Bs[k0 + t][n0 + g];
                bf[nf][1] = Bs[k0 + 4 + t][n0 + g];
            }
            #pragma unroll
            for (int mf = 0; mf < 4; mf++) {
                int m0 = wm * 64 + mf * 16;
                uint32_t a0 = As[k0 + t][m0 + g];
                uint32_t a1 = As[k0 + t][m0 + g + 8];
                uint32_t a2 = As[k0 + 4 + t][m0 + g];
                uint32_t a3 = As[k0 + 4 + t][m0 + g + 8];
                #pragma unroll
                for (int nf = 0; nf < 4; nf++)
                    mma_tf32(acc[mf * 4 + nf], a0, a1, a2, a3, bf[nf][0], bf[nf][1]);
            }
        }
        __syncthreads();
    }
    #pragma unroll
    for (int mf = 0; mf < 4; mf++) {
        #pragma unroll
        for (int nf = 0; nf < 4; nf++) {
            float* c = acc[mf * 4 + nf];
            int cl = wn * 32 + nf * 8 + 2 * t;
            int ncol = nb * 128 + cl;
            int e = ncol / CC;
            #pragma unroll
            for (int h = 0; h < 2; h++) {
                int r = wm * 64 + mf * 16 + g + h * 8;
                float p = sh_probs[r][e];
                float v0 = c[h * 2], v1 = c[h * 2 + 1];
                float g0 = 0.5f * v0 * (1.0f + erff(v0 * 0.70710678118654752f)) * p;
                float g1 = 0.5f * v1 * (1.0f + erff(v1 * 0.70710678118654752f)) * p;
                *(float2*)(g_mid + (size_t)(mb * 128 + r) * N1 + ncol) =
                    make_float2(g0, g1);
            }
        }
    }
}

// ---------------- up GEMM (tf32 tensor cores, pre-converted tiles) ---------
// y = h + alpha * (mid @ Wu').  M=NTOK, N=DD, K=N1.
__global__ __launch_bounds__(256, 2) void up_kernel(const float* __restrict__ x,
                                                    const float* __restrict__ alphap,
                                                    float* __restrict__ out) {
    __shared__ uint32_t As[16][136];
    __shared__ uint32_t Bs[16][136];
    int tid = threadIdx.x;
    int lane = tid & 31, wid = tid >> 5;
    int wm = wid & 1, wn = wid >> 1;
    int g = lane >> 2, t = lane & 3;
    int mb = blockIdx.y, nb = blockIdx.x;

    float acc[16][4];
    #pragma unroll
    for (int i = 0; i < 16; i++)
        #pragma unroll
        for (int j = 0; j < 4; j++) acc[i][j] = 0.0f;

    for (int kb = 0; kb < N1; kb += 16) {
        #pragma unroll
        for (int l = 0; l < 2; l++) {
            int lin4 = tid + 256 * l;
            int row = lin4 >> 2, kq = (lin4 & 3) * 4;
            float4 v = *(const float4*)(g_mid + (size_t)(mb * 128 + row) * N1 + kb + kq);
            As[kq][row]     = f2tf32(v.x);
            As[kq + 1][row] = f2tf32(v.y);
            As[kq + 2][row] = f2tf32(v.z);
            As[kq + 3][row] = f2tf32(v.w);
        }
        #pragma unroll
        for (int l = 0; l < 2; l++) {
            int lin4 = tid + 256 * l;
            int kk = lin4 >> 5, nn = (lin4 & 31) * 4;
            float4 v = *(const float4*)(g_wut + (size_t)(kb + kk) * DD + nb * 128 + nn);
            Bs[kk][nn]     = f2tf32(v.x);
            Bs[kk][nn + 1] = f2tf32(v.y);
            Bs[kk][nn + 2] = f2tf32(v.z);
            Bs[kk][nn + 3] = f2tf32(v.w);
        }
        __syncthreads();
        #pragma unroll
        for (int ks = 0; ks < 2; ks++) {
            int k0 = ks * 8;
            uint32_t bf[4][2];
            #pragma unroll
            for (int nf = 0; nf < 4; nf++) {
                int n0 = wn * 32 + nf * 8;
                bf[nf][0] = Bs[k0 + t][n0 + g];
                bf[nf][1] = Bs[k0 + 4 + t][n0 + g];
            }
            #pragma unroll
            for (int mf = 0; mf < 4; mf++) {
                int m0 = wm * 64 + mf * 16;
                uint32_t a0 = As[k0 + t][m0 + g];
                uint32_t a1 = As[k0 + t][m0 + g + 8];
                uint32_t a2 = As[k0 + 4 + t][m0 + g];
                uint32_t a3 = As[k0 + 4 + t][m0 + g + 8];
                #pragma unroll
                for (int nf = 0; nf < 4; nf++)
                    mma_tf32(acc[mf * 4 + nf], a0, a1, a2, a3, bf[nf][0], bf[nf][1]);
            }
        }
        __syncthreads();
    }
    float alpha = *alphap;
    #pragma unroll
    for (int mf = 0; mf < 4; mf++) {
        #pragma unroll
        for (int nf = 0; nf < 4; nf++) {
            float* c = acc[mf * 4 + nf];
            int cl = wn * 32 + nf * 8 + 2 * t;
            int ncol = nb * 128 + cl;
            #pragma unroll
            for (int h = 0; h < 2; h++) {
                int r = wm * 64 + mf * 16 + g + h * 8;
                int gi = mb * 128 + r;
                int b = gi >> 10;
                int tt = (gi & 1023) + 1;
                size_t ro = ((size_t)b * TT + tt) * DD + ncol;
                float2 hx = *(const float2*)(x + ro);
                *(float2*)(out + ro) = make_float2(fmaf(alpha, c[h * 2], hx.x),
                                                   fmaf(alpha, c[h * 2 + 1], hx.y));
            }
        }
    }
}

// ---------------- launch ----------------
extern "C" void kernel_launch(void* const* d_in, const int* in_sizes, int n_in,
                              void* d_out, int out_size) {
    const float* x     = (const float*)d_in[0];
    const float* Q     = (const float*)d_in[1];
    const float* P     = (const float*)d_in[2];
    const float* gamma = (const float*)d_in[3];
    const float* masks = (const float*)d_in[4];
    const float* bias  = (const float*)d_in[5];
    const float* Wd    = (const float*)d_in[6];
    const float* Wu    = (const float*)d_in[7];
    const float* alpha = (const float*)d_in[8];
    float* out = (float*)d_out;

    const int router_smem = (128 * RZS + EE * RZS) * sizeof(float);  // ~70.2 KB
    cudaFuncSetAttribute(router_kernel,
                         cudaFuncAttributeMaxDynamicSharedMemorySize, router_smem);

    init_kernel<<<(BB * DD / 4 + 2 + 255) / 256, 256>>>(x, out);
    transpose_w<<<2048, 256>>>(Wd, Wu);
    ortho_kernel<<<2 * RR, RR>>>(Q, P);
    router_kernel<<<NTOK / 128, 256, router_smem>>>(x, Q, gamma, masks, bias);
    down_kernel<<<dim3(N1 / 128, NTOK / 128), 256>>>(x);
    up_kernel<<<dim3(DD / 128, NTOK / 128), 256>>>(x, alpha, out);
    finalize_kernel<<<1, 32>>>(out);
}

// round 8
// speedup vs baseline: 3.4007x; 1.4069x over previous
#include <cuda_runtime.h>
#include <math.h>
#include <stdint.h>

#define BB 16
#define TT 1025
#define DD 1024
#define EE 8
#define RR 128
#define CC 192
#define N1 1536            // EE*CC
#define NTOK 16384         // BB*(TT-1)
#define NTOT (16*1025*1024)

// -------- scratch (static device arrays; no allocations) --------
__device__ float g_probs[NTOK * EE];                       // 512 KB
__device__ float g_mid[(size_t)NTOK * N1];                 // ~100.7 MB
__device__ float g_wdt[(size_t)DD * N1];                   // W_down^T: [k][n]
__device__ float g_wut[(size_t)N1 * DD];                   // W_up reshaped: [k=e*C+c][d]
__device__ double g_ortho;                                 // fp64 accumulator
__device__ double g_ent;                                   // fp64 accumulator

// -------- tf32 mma helpers --------
__device__ __forceinline__ uint32_t f2tf32(float f) {
    uint32_t u;
    asm("cvt.rna.tf32.f32 %0, %1;" : "=r"(u) : "f"(f));
    return u;
}
__device__ __forceinline__ void mma_tf32(float* c,
                                         uint32_t a0, uint32_t a1, uint32_t a2, uint32_t a3,
                                         uint32_t b0, uint32_t b1) {
    asm volatile("mma.sync.aligned.m16n8k8.row.col.f32.tf32.tf32.f32 "
                 "{%0,%1,%2,%3}, {%4,%5,%6,%7}, {%8,%9}, {%0,%1,%2,%3};"
                 : "+f"(c[0]), "+f"(c[1]), "+f"(c[2]), "+f"(c[3])
                 : "r"(a0), "r"(a1), "r"(a2), "r"(a3), "r"(b0), "r"(b1));
}
__device__ __forceinline__ void cp_async16(float* smem, const float* gmem) {
    uint32_t s = (uint32_t)__cvta_generic_to_shared(smem);
    asm volatile("cp.async.cg.shared.global [%0], [%1], 16;\n" :: "r"(s), "l"(gmem));
}
#define CP_COMMIT() asm volatile("cp.async.commit_group;\n" ::: "memory")
#define CP_WAIT1()  asm volatile("cp.async.wait_group 1;\n" ::: "memory")
#define CP_WAIT0()  asm volatile("cp.async.wait_group 0;\n" ::: "memory")

// SMEM tile geometry
#define AS_STRIDE 36                // [128][36] per buffer (A as [m][k])
#define BS_STRIDE 136               // [32][136] per buffer (B as [k][n])
#define AS_BUF (128 * AS_STRIDE)    // 4608 floats
#define BS_BUF (32 * BS_STRIDE)     // 4352 floats
#define GEMM_DYN_SMEM ((2 * AS_BUF + 2 * BS_BUF) * sizeof(float))  // 71680 B

// ---------------- init: CLS copy + zero accumulators ----------------
__global__ void init_kernel(const float* __restrict__ x, float* __restrict__ out) {
    int i = blockIdx.x * blockDim.x + threadIdx.x;
    int nvec = BB * DD / 4;
    if (i < nvec) {
        int b = i / (DD / 4);
        int d4 = i % (DD / 4);
        size_t off = (size_t)b * TT * DD + d4 * 4;   // token t=0
        *(float4*)(out + off) = *(const float4*)(x + off);
    } else if (i == nvec) {
        g_ortho = 0.0;
    } else if (i == nvec + 1) {
        g_ent = 0.0;
    }
}

// ---------------- finalize: write scalars ----------------
__global__ void finalize_kernel(float* __restrict__ out) {
    if (threadIdx.x == 0) {
        out[NTOT]     = (float)(0.001 * g_ortho);
        out[NTOT + 1] = (float)(g_ent * (1.0 / (double)NTOK));
    }
}

// ---------------- weight transposes ----------------
__global__ void transpose_w(const float* __restrict__ Wd, const float* __restrict__ Wu) {
    for (int i = blockIdx.x * blockDim.x + threadIdx.x; i < N1 * DD;
         i += gridDim.x * blockDim.x) {
        int n = i / DD, k = i % DD;
        g_wdt[(size_t)k * N1 + n] = Wd[i];
        int c = i % CC;
        int ed = i / CC;
        int d2 = ed % DD;
        int e2 = ed / DD;
        g_wut[(size_t)(e2 * CC + c) * DD + d2] = Wu[i];
    }
}

// ---------------- ortho penalty (splitK=2 fp32 emulation, fp64 sum) -------
__global__ void ortho_kernel(const float* __restrict__ Q, const float* __restrict__ P) {
    const float* M = (blockIdx.x < RR) ? Q : P;
    int i = blockIdx.x & (RR - 1);
    __shared__ float col[DD];
    __shared__ double red[RR];
    for (int d = threadIdx.x; d < DD; d += RR) col[d] = M[(size_t)d * RR + i];
    __syncthreads();
    int j = threadIdx.x;
    float s1 = 0.0f, s2 = 0.0f;
    for (int d = 0; d < DD / 2; d++)
        s1 = fmaf(col[d], M[(size_t)d * RR + j], s1);
    for (int d = DD / 2; d < DD; d++)
        s2 = fmaf(col[d], M[(size_t)d * RR + j], s2);
    float G = s1 + s2;
    double r = (double)G - (j == i ? 1.0 : 0.0);
    red[j] = r * r;
    __syncthreads();
    for (int st = RR / 2; st > 0; st >>= 1) {
        if (j < st) red[j] += red[j + st];
        __syncthreads();
    }
    if (j == 0) atomicAdd(&g_ortho, red[0]);
}

// ---------------- router (tensor-core fused) ----------------
#define RZS 129
__global__ __launch_bounds__(256) void router_kernel(
    const float* __restrict__ x, const float* __restrict__ Q,
    const float* __restrict__ gamma, const float* __restrict__ masks,
    const float* __restrict__ bias) {
    extern __shared__ float sdyn[];
    float* zs = sdyn;                         // 128*129 floats
    float* gmv = sdyn + 128 * RZS;            // 8*129 floats
    uint32_t* As = (uint32_t*)sdyn;           // [16][136] aliased over zs
    uint32_t* Bs = As + 16 * 136;             // [16][136]
    __shared__ size_t rowoff[128];
    __shared__ float entS[128];

    int tid = threadIdx.x;
    int lane = tid & 31, wid = tid >> 5;
    int wm = wid & 1, wn = wid >> 1;
    int g = lane >> 2, t = lane & 3;
    int mb = blockIdx.x;
    int tok0 = mb * 128;

    if (tid < 128) {
        int gi = tok0 + tid;
        int b = gi >> 10;
        int tt = (gi & 1023) + 1;
        rowoff[tid] = ((size_t)b * TT + tt) * DD;
        float mv[EE];
        float mx = -1e30f;
        #pragma unroll
        for (int e = 0; e < EE; e++) { mv[e] = masks[e * RR + tid]; mx = fmaxf(mx, mv[e]); }
        float ss = 0.0f;
        #pragma unroll
        for (int e = 0; e < EE; e++) { mv[e] = expf(mv[e] - mx); ss += mv[e]; }
        float gsc = gamma[tid] / ss;
        #pragma unroll
        for (int e = 0; e < EE; e++) gmv[e * RZS + tid] = mv[e] * gsc;
    }
    __syncthreads();

    float acc[16][4];
    #pragma unroll
    for (int i = 0; i < 16; i++)
        #pragma unroll
        for (int j = 0; j < 4; j++) acc[i][j] = 0.0f;

    for (int kb = 0; kb < DD; kb += 16) {
        #pragma unroll
        for (int l = 0; l < 2; l++) {
            int lin4 = tid + 256 * l;
            int row = lin4 >> 2, kq = (lin4 & 3) * 4;
            float4 v = *(const float4*)(x + rowoff[row] + kb + kq);
            As[(kq) * 136 + row]     = f2tf32(v.x);
            As[(kq + 1) * 136 + row] = f2tf32(v.y);
            As[(kq + 2) * 136 + row] = f2tf32(v.z);
            As[(kq + 3) * 136 + row] = f2tf32(v.w);
        }
        #pragma unroll
        for (int l = 0; l < 2; l++) {
            int lin4 = tid + 256 * l;
            int kk = lin4 >> 5, nn = (lin4 & 31) * 4;
            float4 v = *(const float4*)(Q + (size_t)(kb + kk) * RR + nn);
            Bs[kk * 136 + nn]     = f2tf32(v.x);
            Bs[kk * 136 + nn + 1] = f2tf32(v.y);
            Bs[kk * 136 + nn + 2] = f2tf32(v.z);
            Bs[kk * 136 + nn + 3] = f2tf32(v.w);
        }
        __syncthreads();
        #pragma unroll
        for (int ks = 0; ks < 2; ks++) {
            int k0 = ks * 8;
            uint32_t bf[4][2];
            #pragma unroll
            for (int nf = 0; nf < 4; nf++) {
                int n0 = wn * 32 + nf * 8;
                bf[nf][0] = Bs[(k0 + t) * 136 + n0 + g];
                bf[nf][1] = Bs[(k0 + 4 + t) * 136 + n0 + g];
            }
            #pragma unroll
            for (int mf = 0; mf < 4; mf++) {
                int m0 = wm * 64 + mf * 16;
                uint32_t a0 = As[(k0 + t) * 136 + m0 + g];
                uint32_t a1 = As[(k0 + t) * 136 + m0 + g + 8];
                uint32_t a2 = As[(k0 + 4 + t) * 136 + m0 + g];
                uint32_t a3 = As[(k0 + 4 + t) * 136 + m0 + g + 8];
                #pragma unroll
                for (int nf = 0; nf < 4; nf++)
                    mma_tf32(acc[mf * 4 + nf], a0, a1, a2, a3, bf[nf][0], bf[nf][1]);
            }
        }
        __syncthreads();
    }
    #pragma unroll
    for (int mf = 0; mf < 4; mf++) {
        #pragma unroll
        for (int nf = 0; nf < 4; nf++) {
            float* c = acc[mf * 4 + nf];
            int cl = wn * 32 + nf * 8 + 2 * t;
            #pragma unroll
            for (int h = 0; h < 2; h++) {
                int r = wm * 64 + mf * 16 + g + h * 8;
                zs[r * RZS + cl]     = c[h * 2] * c[h * 2];
                zs[r * RZS + cl + 1] = c[h * 2 + 1] * c[h * 2 + 1];
            }
        }
    }
    __syncthreads();

    if (tid < 128) {
        float s = 0.0f;
        float lg[EE];
        #pragma unroll
        for (int e = 0; e < EE; e++) lg[e] = 0.0f;
        #pragma unroll 4
        for (int r = 0; r < RR; r++) {
            float zq = zs[tid * RZS + r];
            s += zq;
            #pragma unroll
            for (int e = 0; e < EE; e++) lg[e] = fmaf(zq, gmv[e * RZS + r], lg[e]);
        }
        float sinv = 1.0f / (s + 1e-6f);
        float mx = -1e30f;
        #pragma unroll
        for (int e = 0; e < EE; e++) { lg[e] = lg[e] * sinv + bias[e]; mx = fmaxf(mx, lg[e]); }
        float ss = 0.0f;
        #pragma unroll
        for (int e = 0; e < EE; e++) { lg[e] = expf(lg[e] - mx); ss += lg[e]; }
        float inv = 1.0f / ss;
        float hent = 0.0f;
        #pragma unroll
        for (int e = 0; e < EE; e++) {
            float p = lg[e] * inv;
            hent -= p * logf(fmaxf(p, 1e-9f));
            g_probs[(size_t)(tok0 + tid) * EE + e] = p;
        }
        entS[tid] = hent;
    }
    __syncthreads();
    for (int st = 64; st > 0; st >>= 1) {
        if (tid < st && tid + st < 128) entS[tid] += entS[tid + st];
        __syncthreads();
    }
    if (tid == 0) atomicAdd(&g_ent, (double)entS[0]);
}

// ---------------- down GEMM (tf32, cp.async double-buffered BK=32) --------
// mid = gelu(h @ Wd^T) * probs.  M=NTOK, N=N1, K=DD.
__global__ __launch_bounds__(256, 2) void down_kernel(const float* __restrict__ x) {
    extern __shared__ float sm[];
    float* Asf = sm;                      // [2][128][36]  (A as [m][k])
    float* Bsf = sm + 2 * AS_BUF;         // [2][32][136]  (B as [k][n])
    __shared__ float sh_probs[128][EE];
    __shared__ size_t rowoff[128];
    int tid = threadIdx.x;
    int lane = tid & 31, wid = tid >> 5;
    int wm = wid & 1, wn = wid >> 1;
    int g = lane >> 2, t = lane & 3;
    int mb = blockIdx.y, nb = blockIdx.x;

    if (tid < 128) {
        int gi = mb * 128 + tid;
        int b = gi >> 10;
        int tt = (gi & 1023) + 1;
        rowoff[tid] = ((size_t)b * TT + tt) * DD;
    }
    {
        int r = tid >> 1, c4 = (tid & 1) * 4;
        *(float4*)&sh_probs[r][c4] =
            *(const float4*)(g_probs + (size_t)(mb * 128 + r) * EE + c4);
    }
    __syncthreads();

    float acc[16][4];
    #pragma unroll
    for (int i = 0; i < 16; i++)
        #pragma unroll
        for (int j = 0; j < 4; j++) acc[i][j] = 0.0f;

    // prefetch stage 0
    #pragma unroll
    for (int l = 0; l < 4; l++) {
        int lin = tid + 256 * l;
        int row = lin >> 3, kc = (lin & 7) * 4;
        cp_async16(&Asf[row * AS_STRIDE + kc], x + rowoff[row] + kc);
        int kk = lin >> 5, nn = (lin & 31) * 4;
        cp_async16(&Bsf[kk * BS_STRIDE + nn],
                   g_wdt + (size_t)kk * N1 + nb * 128 + nn);
    }
    CP_COMMIT();

    const int NIT = DD / 32;
    for (int it = 0; it < NIT; it++) {
        int buf = it & 1;
        if (it + 1 < NIT) {
            int kb = (it + 1) * 32;
            int nbuf = buf ^ 1;
            #pragma unroll
            for (int l = 0; l < 4; l++) {
                int lin = tid + 256 * l;
                int row = lin >> 3, kc = (lin & 7) * 4;
                cp_async16(&Asf[nbuf * AS_BUF + row * AS_STRIDE + kc],
                           x + rowoff[row] + kb + kc);
                int kk = lin >> 5, nn = (lin & 31) * 4;
                cp_async16(&Bsf[nbuf * BS_BUF + kk * BS_STRIDE + nn],
                           g_wdt + (size_t)(kb + kk) * N1 + nb * 128 + nn);
            }
            CP_COMMIT();
            CP_WAIT1();
        } else {
            CP_WAIT0();
        }
        __syncthreads();
        const float* Ab = Asf + buf * AS_BUF;
        const float* Bb = Bsf + buf * BS_BUF;
        #pragma unroll
        for (int ks = 0; ks < 4; ks++) {
            int k0 = ks * 8;
            uint32_t bfr[4][2];
            #pragma unroll
            for (int nf = 0; nf < 4; nf++) {
                int n0 = wn * 32 + nf * 8;
                bfr[nf][0] = f2tf32(Bb[(k0 + t) * BS_STRIDE + n0 + g]);
                bfr[nf][1] = f2tf32(Bb[(k0 + 4 + t) * BS_STRIDE + n0 + g]);
            }
            #pragma unroll
            for (int mf = 0; mf < 4; mf++) {
                int m0 = wm * 64 + mf * 16;
                uint32_t a0 = f2tf32(Ab[(m0 + g) * AS_STRIDE + k0 + t]);
                uint32_t a1 = f2tf32(Ab[(m0 + g + 8) * AS_STRIDE + k0 + t]);
                uint32_t a2 = f2tf32(Ab[(m0 + g) * AS_STRIDE + k0 + 4 + t]);
                uint32_t a3 = f2tf32(Ab[(m0 + g + 8) * AS_STRIDE + k0 + 4 + t]);
                #pragma unroll
                for (int nf = 0; nf < 4; nf++)
                    mma_tf32(acc[mf * 4 + nf], a0, a1, a2, a3, bfr[nf][0], bfr[nf][1]);
            }
        }
        __syncthreads();
    }
    #pragma unroll
    for (int mf = 0; mf < 4; mf++) {
        #pragma unroll
        for (int nf = 0; nf < 4; nf++) {
            float* c = acc[mf * 4 + nf];
            int cl = wn * 32 + nf * 8 + 2 * t;
            int ncol = nb * 128 + cl;
            int e = ncol / CC;
            #pragma unroll
            for (int h = 0; h < 2; h++) {
                int r = wm * 64 + mf * 16 + g + h * 8;
                float p = sh_probs[r][e];
                float v0 = c[h * 2], v1 = c[h * 2 + 1];
                float g0 = 0.5f * v0 * (1.0f + erff(v0 * 0.70710678118654752f)) * p;
                float g1 = 0.5f * v1 * (1.0f + erff(v1 * 0.70710678118654752f)) * p;
                *(float2*)(g_mid + (size_t)(mb * 128 + r) * N1 + ncol) =
                    make_float2(g0, g1);
            }
        }
    }
}

// ---------------- up GEMM (tf32, cp.async double-buffered BK=32) ----------
// y = h + alpha * (mid @ Wu').  M=NTOK, N=DD, K=N1.
__global__ __launch_bounds__(256, 2) void up_kernel(const float* __restrict__ x,
                                                    const float* __restrict__ alphap,
                                                    float* __restrict__ out) {
    extern __shared__ float sm[];
    float* Asf = sm;                      // [2][128][36]
    float* Bsf = sm + 2 * AS_BUF;         // [2][32][136]
    int tid = threadIdx.x;
    int lane = tid & 31, wid = tid >> 5;
    int wm = wid & 1, wn = wid >> 1;
    int g = lane >> 2, t = lane & 3;
    int mb = blockIdx.y, nb = blockIdx.x;
    const float* amid = g_mid + (size_t)mb * 128 * N1;

    float acc[16][4];
    #pragma unroll
    for (int i = 0; i < 16; i++)
        #pragma unroll
        for (int j = 0; j < 4; j++) acc[i][j] = 0.0f;

    #pragma unroll
    for (int l = 0; l < 4; l++) {
        int lin = tid + 256 * l;
        int row = lin >> 3, kc = (lin & 7) * 4;
        cp_async16(&Asf[row * AS_STRIDE + kc], amid + (size_t)row * N1 + kc);
        int kk = lin >> 5, nn = (lin & 31) * 4;
        cp_async16(&Bsf[kk * BS_STRIDE + nn],
                   g_wut + (size_t)kk * DD + nb * 128 + nn);
    }
    CP_COMMIT();

    const int NIT = N1 / 32;
    for (int it = 0; it < NIT; it++) {
        int buf = it & 1;
        if (it + 1 < NIT) {
            int kb = (it + 1) * 32;
            int nbuf = buf ^ 1;
            #pragma unroll
            for (int l = 0; l < 4; l++) {
                int lin = tid + 256 * l;
                int row = lin >> 3, kc = (lin & 7) * 4;
                cp_async16(&Asf[nbuf * AS_BUF + row * AS_STRIDE + kc],
                           amid + (size_t)row * N1 + kb + kc);
                int kk = lin >> 5, nn = (lin & 31) * 4;
                cp_async16(&Bsf[nbuf * BS_BUF + kk * BS_STRIDE + nn],
                           g_wut + (size_t)(kb + kk) * DD + nb * 128 + nn);
            }
            CP_COMMIT();
            CP_WAIT1();
        } else {
            CP_WAIT0();
        }
        __syncthreads();
        const float* Ab = Asf + buf * AS_BUF;
        const float* Bb = Bsf + buf * BS_BUF;
        #pragma unroll
        for (int ks = 0; ks < 4; ks++) {
            int k0 = ks * 8;
            uint32_t bfr[4][2];
            #pragma unroll
            for (int nf = 0; nf < 4; nf++) {
                int n0 = wn * 32 + nf * 8;
                bfr[nf][0] = f2tf32(Bb[(k0 + t) * BS_STRIDE + n0 + g]);
                bfr[nf][1] = f2tf32(Bb[(k0 + 4 + t) * BS_STRIDE + n0 + g]);
            }
            #pragma unroll
            for (int mf = 0; mf < 4; mf++) {
                int m0 = wm * 64 + mf * 16;
                uint32_t a0 = f2tf32(Ab[(m0 + g) * AS_STRIDE + k0 + t]);
                uint32_t a1 = f2tf32(Ab[(m0 + g + 8) * AS_STRIDE + k0 + t]);
                uint32_t a2 = f2tf32(Ab[(m0 + g) * AS_STRIDE + k0 + 4 + t]);
                uint32_t a3 = f2tf32(Ab[(m0 + g + 8) * AS_STRIDE + k0 + 4 + t]);
                #pragma unroll
                for (int nf = 0; nf < 4; nf++)
                    mma_tf32(acc[mf * 4 + nf], a0, a1, a2, a3, bfr[nf][0], bfr[nf][1]);
            }
        }
        __syncthreads();
    }
    float alpha = *alphap;
    #pragma unroll
    for (int mf = 0; mf < 4; mf++) {
        #pragma unroll
        for (int nf = 0; nf < 4; nf++) {
            float* c = acc[mf * 4 + nf];
            int cl = wn * 32 + nf * 8 + 2 * t;
            int ncol = nb * 128 + cl;
            #pragma unroll
            for (int h = 0; h < 2; h++) {
                int r = wm * 64 + mf * 16 + g + h * 8;
                int gi = mb * 128 + r;
                int b = gi >> 10;
                int tt = (gi & 1023) + 1;
                size_t ro = ((size_t)b * TT + tt) * DD + ncol;
                float2 hx = *(const float2*)(x + ro);
                *(float2*)(out + ro) = make_float2(fmaf(alpha, c[h * 2], hx.x),
                                                   fmaf(alpha, c[h * 2 + 1], hx.y));
            }
        }
    }
}

// ---------------- launch ----------------
extern "C" void kernel_launch(void* const* d_in, const int* in_sizes, int n_in,
                              void* d_out, int out_size) {
    const float* x     = (const float*)d_in[0];
    const float* Q     = (const float*)d_in[1];
    const float* P     = (const float*)d_in[2];
    const float* gamma = (const float*)d_in[3];
    const float* masks = (const float*)d_in[4];
    const float* bias  = (const float*)d_in[5];
    const float* Wd    = (const float*)d_in[6];
    const float* Wu    = (const float*)d_in[7];
    const float* alpha = (const float*)d_in[8];
    float* out = (float*)d_out;

    const int router_smem = (128 * RZS + EE * RZS) * sizeof(float);  // ~70.2 KB
    cudaFuncSetAttribute(router_kernel,
                         cudaFuncAttributeMaxDynamicSharedMemorySize, router_smem);
    cudaFuncSetAttribute(down_kernel,
                         cudaFuncAttributeMaxDynamicSharedMemorySize, GEMM_DYN_SMEM);
    cudaFuncSetAttribute(up_kernel,
                         cudaFuncAttributeMaxDynamicSharedMemorySize, GEMM_DYN_SMEM);

    init_kernel<<<(BB * DD / 4 + 2 + 255) / 256, 256>>>(x, out);
    transpose_w<<<2048, 256>>>(Wd, Wu);
    ortho_kernel<<<2 * RR, RR>>>(Q, P);
    router_kernel<<<NTOK / 128, 256, router_smem>>>(x, Q, gamma, masks, bias);
    down_kernel<<<dim3(N1 / 128, NTOK / 128), 256, GEMM_DYN_SMEM>>>(x);
    up_kernel<<<dim3(DD / 128, NTOK / 128), 256, GEMM_DYN_SMEM>>>(x, alpha, out);
    finalize_kernel<<<1, 32>>>(out);
}

// round 10
// speedup vs baseline: 3.7810x; 1.1118x over previous
#include <cuda_runtime.h>
#include <math.h>
#include <stdint.h>

#define BB 16
#define TT 1025
#define DD 1024
#define EE 8
#define RR 128
#define CC 192
#define N1 1536            // EE*CC
#define NTOK 16384         // BB*(TT-1)
#define NTOT (16*1025*1024)

// -------- scratch (static device arrays; no allocations) --------
__device__ float g_probs[NTOK * EE];                       // 512 KB
__device__ float g_mid[(size_t)NTOK * N1];                 // ~100.7 MB (tf32-rounded)
__device__ float g_xt[(size_t)NTOK * DD];                  // 67 MB, tf32-rounded compact h
__device__ float g_wdt[(size_t)DD * N1];                   // tf32(W_down^T): [k][n]
__device__ float g_wut[(size_t)N1 * DD];                   // tf32(W_up resh): [k=e*C+c][d]
__device__ float g_qt[(size_t)DD * RR];                    // tf32(Q): [k][r]
__device__ double g_ortho;                                 // fp64 accumulator
__device__ double g_ent;                                   // fp64 accumulator

// -------- tf32 mma helpers --------
__device__ __forceinline__ uint32_t f2tf32(float f) {
    uint32_t u;
    asm("cvt.rna.tf32.f32 %0, %1;" : "=r"(u) : "f"(f));
    return u;
}
__device__ __forceinline__ void mma_tf32(float* c,
                                         uint32_t a0, uint32_t a1, uint32_t a2, uint32_t a3,
                                         uint32_t b0, uint32_t b1) {
    asm volatile("mma.sync.aligned.m16n8k8.row.col.f32.tf32.tf32.f32 "
                 "{%0,%1,%2,%3}, {%4,%5,%6,%7}, {%8,%9}, {%0,%1,%2,%3};"
                 : "+f"(c[0]), "+f"(c[1]), "+f"(c[2]), "+f"(c[3])
                 : "r"(a0), "r"(a1), "r"(a2), "r"(a3), "r"(b0), "r"(b1));
}
__device__ __forceinline__ void cp_async16(float* smem, const float* gmem) {
    uint32_t s = (uint32_t)__cvta_generic_to_shared(smem);
    asm volatile("cp.async.cg.shared.global [%0], [%1], 16;\n" :: "r"(s), "l"(gmem));
}
#define CP_COMMIT() asm volatile("cp.async.commit_group;\n" ::: "memory")
#define CP_WAIT1()  asm volatile("cp.async.wait_group 1;\n" ::: "memory")
#define CP_WAIT0()  asm volatile("cp.async.wait_group 0;\n" ::: "memory")

// SMEM tile geometry
#define AS_STRIDE 36                // [128][36] per buffer (A as [m][k])
#define BS_STRIDE 136               // [32][136] per buffer (B as [k][n])
#define AS_BUF (128 * AS_STRIDE)
#define BS_BUF (32 * BS_STRIDE)
#define GEMM_DYN_SMEM ((2 * AS_BUF + 2 * BS_BUF) * sizeof(float))          // 71680 B
#define RZS 129
#define ROUTER_DYN_SMEM (GEMM_DYN_SMEM + EE * RZS * sizeof(float))          // +4128 B

// ---------------- init: CLS copy + zero accumulators ----------------
__global__ void init_kernel(const float* __restrict__ x, float* __restrict__ out) {
    int i = blockIdx.x * blockDim.x + threadIdx.x;
    int nvec = BB * DD / 4;
    if (i < nvec) {
        int b = i / (DD / 4);
        int d4 = i % (DD / 4);
        size_t off = (size_t)b * TT * DD + d4 * 4;   // token t=0
        *(float4*)(out + off) = *(const float4*)(x + off);
    } else if (i == nvec) {
        g_ortho = 0.0;
    } else if (i == nvec + 1) {
        g_ent = 0.0;
    }
}

// ---------------- finalize: write scalars ----------------
__global__ void finalize_kernel(float* __restrict__ out) {
    if (threadIdx.x == 0) {
        out[NTOT]     = (float)(0.001 * g_ortho);
        out[NTOT + 1] = (float)(g_ent * (1.0 / (double)NTOK));
    }
}

// ---------------- x -> compact tf32-rounded g_xt ----------------
__global__ void xconvert_kernel(const float* __restrict__ x) {
    int i = blockIdx.x * blockDim.x + threadIdx.x;   // one float4 per thread
    if (i < NTOK * DD / 4) {
        int tok = i / (DD / 4);
        int d4 = (i % (DD / 4)) * 4;
        int b = tok >> 10;
        int t = (tok & 1023) + 1;
        float4 v = *(const float4*)(x + ((size_t)b * TT + t) * DD + d4);
        float4 o;
        o.x = __uint_as_float(f2tf32(v.x));
        o.y = __uint_as_float(f2tf32(v.y));
        o.z = __uint_as_float(f2tf32(v.z));
        o.w = __uint_as_float(f2tf32(v.w));
        *(float4*)(g_xt + (size_t)tok * DD + d4) = o;
    }
}

// ---------------- weight transposes (pre-rounded to tf32) ----------------
__global__ void transpose_w(const float* __restrict__ Wd, const float* __restrict__ Wu,
                            const float* __restrict__ Q) {
    for (int i = blockIdx.x * blockDim.x + threadIdx.x; i < N1 * DD;
         i += gridDim.x * blockDim.x) {
        int n = i / DD, k = i % DD;
        g_wdt[(size_t)k * N1 + n] = __uint_as_float(f2tf32(Wd[i]));
        int c = i % CC;
        int ed = i / CC;
        int d2 = ed % DD;
        int e2 = ed / DD;
        g_wut[(size_t)(e2 * CC + c) * DD + d2] = __uint_as_float(f2tf32(Wu[i]));
        if (i < DD * RR) g_qt[i] = __uint_as_float(f2tf32(Q[i]));
    }
}

// ---------------- ortho penalty (splitK=2 fp32 emulation, fp64 sum) -------
__global__ void ortho_kernel(const float* __restrict__ Q, const float* __restrict__ P) {
    const float* M = (blockIdx.x < RR) ? Q : P;
    int i = blockIdx.x & (RR - 1);
    __shared__ float col[DD];
    __shared__ double red[RR];
    for (int d = threadIdx.x; d < DD; d += RR) col[d] = M[(size_t)d * RR + i];
    __syncthreads();
    int j = threadIdx.x;
    float s1 = 0.0f, s2 = 0.0f;
    for (int d = 0; d < DD / 2; d++)
        s1 = fmaf(col[d], M[(size_t)d * RR + j], s1);
    for (int d = DD / 2; d < DD; d++)
        s2 = fmaf(col[d], M[(size_t)d * RR + j], s2);
    float G = s1 + s2;
    double r = (double)G - (j == i ? 1.0 : 0.0);
    red[j] = r * r;
    __syncthreads();
    for (int st = RR / 2; st > 0; st >>= 1) {
        if (j < st) red[j] += red[j + st];
        __syncthreads();
    }
    if (j == 0) atomicAdd(&g_ortho, red[0]);
}

// ---------------- router (pipelined tf32 GEMM + fused softmax) -------------
// One CTA = 128 tokens, full R=128, K=1024. A=g_xt, B=g_qt (both pre-rounded).
__global__ __launch_bounds__(256) void router_kernel(
    const float* __restrict__ gamma, const float* __restrict__ masks,
    const float* __restrict__ bias) {
    extern __shared__ float sm[];
    float* Asf = sm;                          // [2][128][36]
    float* Bsf = sm + 2 * AS_BUF;             // [2][32][136]
    float* gmv = sm + 2 * AS_BUF + 2 * BS_BUF; // [8][129]
    float* zs = sm;                           // [128][129] aliased over GEMM bufs
    __shared__ float entS[128];

    int tid = threadIdx.x;
    int lane = tid & 31, wid = tid >> 5;
    int wm = wid & 1, wn = wid >> 1;
    int g = lane >> 2, t = lane & 3;
    int tok0 = blockIdx.x * 128;
    const float* arow = g_xt + (size_t)tok0 * DD;

    if (tid < 128) {
        float mv[EE];
        float mx = -1e30f;
        #pragma unroll
        for (int e = 0; e < EE; e++) { mv[e] = masks[e * RR + tid]; mx = fmaxf(mx, mv[e]); }
        float ss = 0.0f;
        #pragma unroll
        for (int e = 0; e < EE; e++) { mv[e] = expf(mv[e] - mx); ss += mv[e]; }
        float gsc = gamma[tid] / ss;
        #pragma unroll
        for (int e = 0; e < EE; e++) gmv[e * RZS + tid] = mv[e] * gsc;
    }

    float acc[16][4];
    #pragma unroll
    for (int i = 0; i < 16; i++)
        #pragma unroll
        for (int j = 0; j < 4; j++) acc[i][j] = 0.0f;

    #pragma unroll
    for (int l = 0; l < 4; l++) {
        int lin = tid + 256 * l;
        int row = lin >> 3, kc = (lin & 7) * 4;
        cp_async16(&Asf[row * AS_STRIDE + kc], arow + (size_t)row * DD + kc);
        int kk = lin >> 5, nn = (lin & 31) * 4;
        cp_async16(&Bsf[kk * BS_STRIDE + nn], g_qt + (size_t)kk * RR + nn);
    }
    CP_COMMIT();

    const int NIT = DD / 32;
    for (int it = 0; it < NIT; it++) {
        int buf = it & 1;
        if (it + 1 < NIT) {
            int kb = (it + 1) * 32;
            int nbuf = buf ^ 1;
            #pragma unroll
            for (int l = 0; l < 4; l++) {
                int lin = tid + 256 * l;
                int row = lin >> 3, kc = (lin & 7) * 4;
                cp_async16(&Asf[nbuf * AS_BUF + row * AS_STRIDE + kc],
                           arow + (size_t)row * DD + kb + kc);
                int kk = lin >> 5, nn = (lin & 31) * 4;
                cp_async16(&Bsf[nbuf * BS_BUF + kk * BS_STRIDE + nn],
                           g_qt + (size_t)(kb + kk) * RR + nn);
            }
            CP_COMMIT();
            CP_WAIT1();
        } else {
            CP_WAIT0();
        }
        __syncthreads();
        const uint32_t* Ab = (const uint32_t*)(Asf + buf * AS_BUF);
        const uint32_t* Bb = (const uint32_t*)(Bsf + buf * BS_BUF);
        #pragma unroll
        for (int ks = 0; ks < 4; ks++) {
            int k0 = ks * 8;
            uint32_t bfr[4][2];
            #pragma unroll
            for (int nf = 0; nf < 4; nf++) {
                int n0 = wn * 32 + nf * 8;
                bfr[nf][0] = Bb[(k0 + t) * BS_STRIDE + n0 + g];
                bfr[nf][1] = Bb[(k0 + 4 + t) * BS_STRIDE + n0 + g];
            }
            #pragma unroll
            for (int mf = 0; mf < 4; mf++) {
                int m0 = wm * 64 + mf * 16;
                uint32_t a0 = Ab[(m0 + g) * AS_STRIDE + k0 + t];
                uint32_t a1 = Ab[(m0 + g + 8) * AS_STRIDE + k0 + t];
                uint32_t a2 = Ab[(m0 + g) * AS_STRIDE + k0 + 4 + t];
                uint32_t a3 = Ab[(m0 + g + 8) * AS_STRIDE + k0 + 4 + t];
                #pragma unroll
                for (int nf = 0; nf < 4; nf++)
                    mma_tf32(acc[mf * 4 + nf], a0, a1, a2, a3, bfr[nf][0], bfr[nf][1]);
            }
        }
        __syncthreads();
    }
    // write z^2 into zs (aliased; all reads done)
    #pragma unroll
    for (int mf = 0; mf < 4; mf++) {
        #pragma unroll
        for (int nf = 0; nf < 4; nf++) {
            float* c = acc[mf * 4 + nf];
            int cl = wn * 32 + nf * 8 + 2 * t;
            #pragma unroll
            for (int h = 0; h < 2; h++) {
                int r = wm * 64 + mf * 16 + g + h * 8;
                zs[r * RZS + cl]     = c[h * 2] * c[h * 2];
                zs[r * RZS + cl + 1] = c[h * 2 + 1] * c[h * 2 + 1];
            }
        }
    }
    __syncthreads();

    if (tid < 128) {
        float s = 0.0f;
        float lg[EE];
        #pragma unroll
        for (int e = 0; e < EE; e++) lg[e] = 0.0f;
        #pragma unroll 4
        for (int r = 0; r < RR; r++) {
            float zq = zs[tid * RZS + r];
            s += zq;
            #pragma unroll
            for (int e = 0; e < EE; e++) lg[e] = fmaf(zq, gmv[e * RZS + r], lg[e]);
        }
        float sinv = 1.0f / (s + 1e-6f);
        float mx = -1e30f;
        #pragma unroll
        for (int e = 0; e < EE; e++) { lg[e] = lg[e] * sinv + bias[e]; mx = fmaxf(mx, lg[e]); }
        float ss = 0.0f;
        #pragma unroll
        for (int e = 0; e < EE; e++) { lg[e] = expf(lg[e] - mx); ss += lg[e]; }
        float inv = 1.0f / ss;
        float hent = 0.0f;
        #pragma unroll
        for (int e = 0; e < EE; e++) {
            float p = lg[e] * inv;
            hent -= p * logf(fmaxf(p, 1e-9f));
            g_probs[(size_t)(tok0 + tid) * EE + e] = p;
        }
        entS[tid] = hent;
    }
    __syncthreads();
    for (int st = 64; st > 0; st >>= 1) {
        if (tid < st && tid + st < 128) entS[tid] += entS[tid + st];
        __syncthreads();
    }
    if (tid == 0) atomicAdd(&g_ent, (double)entS[0]);
}

// ---------------- down GEMM (pipelined tf32, no in-loop cvt) --------------
__global__ __launch_bounds__(256, 2) void down_kernel() {
    extern __shared__ float sm[];
    float* Asf = sm;
    float* Bsf = sm + 2 * AS_BUF;
    __shared__ float sh_probs[128][EE];
    int tid = threadIdx.x;
    int lane = tid & 31, wid = tid >> 5;
    int wm = wid & 1, wn = wid >> 1;
    int g = lane >> 2, t = lane & 3;
    int mb = blockIdx.y, nb = blockIdx.x;
    const float* arow = g_xt + (size_t)mb * 128 * DD;

    {
        int r = tid >> 1, c4 = (tid & 1) * 4;
        *(float4*)&sh_probs[r][c4] =
            *(const float4*)(g_probs + (size_t)(mb * 128 + r) * EE + c4);
    }

    float acc[16][4];
    #pragma unroll
    for (int i = 0; i < 16; i++)
        #pragma unroll
        for (int j = 0; j < 4; j++) acc[i][j] = 0.0f;

    #pragma unroll
    for (int l = 0; l < 4; l++) {
        int lin = tid + 256 * l;
        int row = lin >> 3, kc = (lin & 7) * 4;
        cp_async16(&Asf[row * AS_STRIDE + kc], arow + (size_t)row * DD + kc);
        int kk = lin >> 5, nn = (lin & 31) * 4;
        cp_async16(&Bsf[kk * BS_STRIDE + nn],
                   g_wdt + (size_t)kk * N1 + nb * 128 + nn);
    }
    CP_COMMIT();

    const int NIT = DD / 32;
    for (int it = 0; it < NIT; it++) {
        int buf = it & 1;
        if (it + 1 < NIT) {
            int kb = (it + 1) * 32;
            int nbuf = buf ^ 1;
            #pragma unroll
            for (int l = 0; l < 4; l++) {
                int lin = tid + 256 * l;
                int row = lin >> 3, kc = (lin & 7) * 4;
                cp_async16(&Asf[nbuf * AS_BUF + row * AS_STRIDE + kc],
                           arow + (size_t)row * DD + kb + kc);
                int kk = lin >> 5, nn = (lin & 31) * 4;
                cp_async16(&Bsf[nbuf * BS_BUF + kk * BS_STRIDE + nn],
                           g_wdt + (size_t)(kb + kk) * N1 + nb * 128 + nn);
            }
            CP_COMMIT();
            CP_WAIT1();
        } else {
            CP_WAIT0();
        }
        __syncthreads();
        const uint32_t* Ab = (const uint32_t*)(Asf + buf * AS_BUF);
        const uint32_t* Bb = (const uint32_t*)(Bsf + buf * BS_BUF);
        #pragma unroll
        for (int ks = 0; ks < 4; ks++) {
            int k0 = ks * 8;
            uint32_t bfr[4][2];
            #pragma unroll
            for (int nf = 0; nf < 4; nf++) {
                int n0 = wn * 32 + nf * 8;
                bfr[nf][0] = Bb[(k0 + t) * BS_STRIDE + n0 + g];
                bfr[nf][1] = Bb[(k0 + 4 + t) * BS_STRIDE + n0 + g];
            }
            #pragma unroll
            for (int mf = 0; mf < 4; mf++) {
                int m0 = wm * 64 + mf * 16;
                uint32_t a0 = Ab[(m0 + g) * AS_STRIDE + k0 + t];
                uint32_t a1 = Ab[(m0 + g + 8) * AS_STRIDE + k0 + t];
                uint32_t a2 = Ab[(m0 + g) * AS_STRIDE + k0 + 4 + t];
                uint32_t a3 = Ab[(m0 + g + 8) * AS_STRIDE + k0 + 4 + t];
                #pragma unroll
                for (int nf = 0; nf < 4; nf++)
                    mma_tf32(acc[mf * 4 + nf], a0, a1, a2, a3, bfr[nf][0], bfr[nf][1]);
            }
        }
        __syncthreads();
    }
    #pragma unroll
    for (int mf = 0; mf < 4; mf++) {
        #pragma unroll
        for (int nf = 0; nf < 4; nf++) {
            float* c = acc[mf * 4 + nf];
            int cl = wn * 32 + nf * 8 + 2 * t;
            int ncol = nb * 128 + cl;
            int e = ncol / CC;
            #pragma unroll
            for (int h = 0; h < 2; h++) {
                int r = wm * 64 + mf * 16 + g + h * 8;
                float p = sh_probs[r][e];
                float v0 = c[h * 2], v1 = c[h * 2 + 1];
                float g0 = 0.5f * v0 * (1.0f + erff(v0 * 0.70710678118654752f)) * p;
                float g1 = 0.5f * v1 * (1.0f + erff(v1 * 0.70710678118654752f)) * p;
                // store tf32-rounded so up's A-loads need no cvt
                *(float2*)(g_mid + (size_t)(mb * 128 + r) * N1 + ncol) =
                    make_float2(__uint_as_float(f2tf32(g0)), __uint_as_float(f2tf32(g1)));
            }
        }
    }
}

// ---------------- up GEMM (pipelined tf32, no in-loop cvt) ----------------
__global__ __launch_bounds__(256, 2) void up_kernel(const float* __restrict__ x,
                                                    const float* __restrict__ alphap,
                                                    float* __restrict__ out) {
    extern __shared__ float sm[];
    float* Asf = sm;
    float* Bsf = sm + 2 * AS_BUF;
    int tid = threadIdx.x;
    int lane = tid & 31, wid = tid >> 5;
    int wm = wid & 1, wn = wid >> 1;
    int g = lane >> 2, t = lane & 3;
    int mb = blockIdx.y, nb = blockIdx.x;
    const float* amid = g_mid + (size_t)mb * 128 * N1;

    float acc[16][4];
    #pragma unroll
    for (int i = 0; i < 16; i++)
        #pragma unroll
        for (int j = 0; j < 4; j++) acc[i][j] = 0.0f;

    #pragma unroll
    for (int l = 0; l < 4; l++) {
        int lin = tid + 256 * l;
        int row = lin >> 3, kc = (lin & 7) * 4;
        cp_async16(&Asf[row * AS_STRIDE + kc], amid + (size_t)row * N1 + kc);
        int kk = lin >> 5, nn = (lin & 31) * 4;
        cp_async16(&Bsf[kk * BS_STRIDE + nn],
                   g_wut + (size_t)kk * DD + nb * 128 + nn);
    }
    CP_COMMIT();

    const int NIT = N1 / 32;
    for (int it = 0; it < NIT; it++) {
        int buf = it & 1;
        if (it + 1 < NIT) {
            int kb = (it + 1) * 32;
            int nbuf = buf ^ 1;
            #pragma unroll
            for (int l = 0; l < 4; l++) {
                int lin = tid + 256 * l;
                int row = lin >> 3, kc = (lin & 7) * 4;
                cp_async16(&Asf[nbuf * AS_BUF + row * AS_STRIDE + kc],
                           amid + (size_t)row * N1 + kb + kc);
                int kk = lin >> 5, nn = (lin & 31) * 4;
                cp_async16(&Bsf[nbuf * BS_BUF + kk * BS_STRIDE + nn],
                           g_wut + (size_t)(kb + kk) * DD + nb * 128 + nn);
            }
            CP_COMMIT();
            CP_WAIT1();
        } else {
            CP_WAIT0();
        }
        __syncthreads();
        const uint32_t* Ab = (const uint32_t*)(Asf + buf * AS_BUF);
        const uint32_t* Bb = (const uint32_t*)(Bsf + buf * BS_BUF);
        #pragma unroll
        for (int ks = 0; ks < 4; ks++) {
            int k0 = ks * 8;
            uint32_t bfr[4][2];
            #pragma unroll
            for (int nf = 0; nf < 4; nf++) {
                int n0 = wn * 32 + nf * 8;
                bfr[nf][0] = Bb[(k0 + t) * BS_STRIDE + n0 + g];
                bfr[nf][1] = Bb[(k0 + 4 + t) * BS_STRIDE + n0 + g];
            }
            #pragma unroll
            for (int mf = 0; mf < 4; mf++) {
                int m0 = wm * 64 + mf * 16;
                uint32_t a0 = Ab[(m0 + g) * AS_STRIDE + k0 + t];
                uint32_t a1 = Ab[(m0 + g + 8) * AS_STRIDE + k0 + t];
                uint32_t a2 = Ab[(m0 + g) * AS_STRIDE + k0 + 4 + t];
                uint32_t a3 = Ab[(m0 + g + 8) * AS_STRIDE + k0 + 4 + t];
                #pragma unroll
                for (int nf = 0; nf < 4; nf++)
                    mma_tf32(acc[mf * 4 + nf], a0, a1, a2, a3, bfr[nf][0], bfr[nf][1]);
            }
        }
        __syncthreads();
    }
    float alpha = *alphap;
    #pragma unroll
    for (int mf = 0; mf < 4; mf++) {
        #pragma unroll
        for (int nf = 0; nf < 4; nf++) {
            float* c = acc[mf * 4 + nf];
            int cl = wn * 32 + nf * 8 + 2 * t;
            int ncol = nb * 128 + cl;
            #pragma unroll
            for (int h = 0; h < 2; h++) {
                int r = wm * 64 + mf * 16 + g + h * 8;
                int gi = mb * 128 + r;
                int b = gi >> 10;
                int tt = (gi & 1023) + 1;
                size_t ro = ((size_t)b * TT + tt) * DD + ncol;
                float2 hx = *(const float2*)(x + ro);
                *(float2*)(out + ro) = make_float2(fmaf(alpha, c[h * 2], hx.x),
                                                   fmaf(alpha, c[h * 2 + 1], hx.y));
            }
        }
    }
}

// ---------------- launch ----------------
extern "C" void kernel_launch(void* const* d_in, const int* in_sizes, int n_in,
                              void* d_out, int out_size) {
    const float* x     = (const float*)d_in[0];
    const float* Q     = (const float*)d_in[1];
    const float* P     = (const float*)d_in[2];
    const float* gamma = (const float*)d_in[3];
    const float* masks = (const float*)d_in[4];
    const float* bias  = (const float*)d_in[5];
    const float* Wd    = (const float*)d_in[6];
    const float* Wu    = (const float*)d_in[7];
    const float* alpha = (const float*)d_in[8];
    float* out = (float*)d_out;

    cudaFuncSetAttribute(router_kernel,
                         cudaFuncAttributeMaxDynamicSharedMemorySize, ROUTER_DYN_SMEM);
    cudaFuncSetAttribute(down_kernel,
                         cudaFuncAttributeMaxDynamicSharedMemorySize, GEMM_DYN_SMEM);
    cudaFuncSetAttribute(up_kernel,
                         cudaFuncAttributeMaxDynamicSharedMemorySize, GEMM_DYN_SMEM);

    init_kernel<<<(BB * DD / 4 + 2 + 255) / 256, 256>>>(x, out);
    xconvert_kernel<<<(NTOK * DD / 4 + 255) / 256, 256>>>(x);
    transpose_w<<<2048, 256>>>(Wd, Wu, Q);
    ortho_kernel<<<2 * RR, RR>>>(Q, P);
    router_kernel<<<NTOK / 128, 256, ROUTER_DYN_SMEM>>>(gamma, masks, bias);
    down_kernel<<<dim3(N1 / 128, NTOK / 128), 256, GEMM_DYN_SMEM>>>();
    up_kernel<<<dim3(DD / 128, NTOK / 128), 256, GEMM_DYN_SMEM>>>(x, alpha, out);
    finalize_kernel<<<1, 32>>>(out);
}

// round 11
// speedup vs baseline: 6.1187x; 1.6183x over previous
#include <cuda_runtime.h>
#include <cuda_fp16.h>
#include <math.h>
#include <stdint.h>

#define BB 16
#define TT 1025
#define DD 1024
#define EE 8
#define RR 128
#define CC 192
#define N1 1536            // EE*CC
#define NTOK 16384         // BB*(TT-1)
#define NTOT (16*1025*1024)

// -------- scratch (static device arrays; no allocations) --------
__device__ float g_probs[NTOK * EE];                           // 512 KB
__device__ __half g_xth[(size_t)NTOK * DD];                    // 33.5 MB fp16 compact h
__device__ __half g_midh[(size_t)NTOK * N1];                   // 50 MB fp16 mid
__device__ uint32_t g_wdt2[(size_t)(DD / 2) * N1];             // half2 [k/2][n]
__device__ uint32_t g_wut2[(size_t)(N1 / 2) * DD];             // half2 [k/2][d]
__device__ uint32_t g_qt2[(size_t)(DD / 2) * RR];              // half2 [k/2][r]
__device__ double g_ortho;
__device__ double g_ent;

// -------- fp16 mma helpers --------
__device__ __forceinline__ void mma_f16(float* c,
                                        uint32_t a0, uint32_t a1, uint32_t a2, uint32_t a3,
                                        uint32_t b0, uint32_t b1) {
    asm volatile("mma.sync.aligned.m16n8k16.row.col.f32.f16.f16.f32 "
                 "{%0,%1,%2,%3}, {%4,%5,%6,%7}, {%8,%9}, {%0,%1,%2,%3};"
                 : "+f"(c[0]), "+f"(c[1]), "+f"(c[2]), "+f"(c[3])
                 : "r"(a0), "r"(a1), "r"(a2), "r"(a3), "r"(b0), "r"(b1));
}
__device__ __forceinline__ void cp_async16(void* smem, const void* gmem) {
    uint32_t s = (uint32_t)__cvta_generic_to_shared(smem);
    asm volatile("cp.async.cg.shared.global [%0], [%1], 16;\n" :: "r"(s), "l"(gmem));
}
#define CP_COMMIT() asm volatile("cp.async.commit_group;\n" ::: "memory")
#define CP_WAIT1()  asm volatile("cp.async.wait_group 1;\n" ::: "memory")
#define CP_WAIT0()  asm volatile("cp.async.wait_group 0;\n" ::: "memory")

// SMEM geometry (per buffer): A [128][40] halves, B [16][136] half2(u32)
#define ASH_STRIDE 40
#define BS2_STRIDE 136
#define ASH_BUF (128 * ASH_STRIDE)   // halves
#define BS2_BUF (16 * BS2_STRIDE)    // u32
#define GEMM_DYN_SMEM (2 * ASH_BUF * 2 + 2 * BS2_BUF * 4)      // 37888 B
#define RZS 129
#define ROUTER_DYN_SMEM ((128 * RZS + EE * RZS) * 4)           // 70176 B (zs+gmv alias GEMM bufs)

// ---------------- init: CLS copy + zero accumulators ----------------
__global__ void init_kernel(const float* __restrict__ x, float* __restrict__ out) {
    int i = blockIdx.x * blockDim.x + threadIdx.x;
    int nvec = BB * DD / 4;
    if (i < nvec) {
        int b = i / (DD / 4);
        int d4 = i % (DD / 4);
        size_t off = (size_t)b * TT * DD + d4 * 4;
        *(float4*)(out + off) = *(const float4*)(x + off);
    } else if (i == nvec) {
        g_ortho = 0.0;
    } else if (i == nvec + 1) {
        g_ent = 0.0;
    }
}

// ---------------- finalize ----------------
__global__ void finalize_kernel(float* __restrict__ out) {
    if (threadIdx.x == 0) {
        out[NTOT]     = (float)(0.001 * g_ortho);
        out[NTOT + 1] = (float)(g_ent * (1.0 / (double)NTOK));
    }
}

// ---------------- x -> compact fp16 g_xth ----------------
__global__ void xconvert_kernel(const float* __restrict__ x) {
    int i = blockIdx.x * blockDim.x + threadIdx.x;
    if (i < NTOK * DD / 4) {
        int tok = i / (DD / 4);
        int d4 = (i % (DD / 4)) * 4;
        int b = tok >> 10;
        int t = (tok & 1023) + 1;
        float4 v = *(const float4*)(x + ((size_t)b * TT + t) * DD + d4);
        __half2 h0 = __floats2half2_rn(v.x, v.y);
        __half2 h1 = __floats2half2_rn(v.z, v.w);
        uint2 o = make_uint2(*(uint32_t*)&h0, *(uint32_t*)&h1);
        *(uint2*)(g_xth + (size_t)tok * DD + d4) = o;
    }
}

// ---------------- weights -> fp16 k-pair-interleaved ----------------
__global__ void wconvert_kernel(const float* __restrict__ Wd, const float* __restrict__ Wu,
                                const float* __restrict__ Q) {
    const int NW = (DD / 2) * N1;   // == (N1/2)*DD
    for (int i = blockIdx.x * blockDim.x + threadIdx.x; i < NW;
         i += gridDim.x * blockDim.x) {
        {   // g_wdt2[k2][n] from Wd[n][2k2], Wd[n][2k2+1]
            int k2 = i / N1, n = i % N1;
            __half2 h = __floats2half2_rn(Wd[(size_t)n * DD + 2 * k2],
                                          Wd[(size_t)n * DD + 2 * k2 + 1]);
            g_wdt2[i] = *(uint32_t*)&h;
        }
        {   // g_wut2[k2][d]; k=e*CC+c, pairs stay within one expert (CC even)
            int k2 = i / DD, d = i % DD;
            int k = 2 * k2;
            int e = k / CC, c = k % CC;
            __half2 h = __floats2half2_rn(Wu[((size_t)e * DD + d) * CC + c],
                                          Wu[((size_t)e * DD + d) * CC + c + 1]);
            g_wut2[i] = *(uint32_t*)&h;
        }
        if (i < (DD / 2) * RR) {   // g_qt2[k2][r]
            int k2 = i / RR, r = i % RR;
            __half2 h = __floats2half2_rn(Q[(size_t)(2 * k2) * RR + r],
                                          Q[(size_t)(2 * k2 + 1) * RR + r]);
            g_qt2[i] = *(uint32_t*)&h;
        }
    }
}

// ---------------- ortho penalty (splitK=2 fp32 emulation, fp64 sum) -------
__global__ void ortho_kernel(const float* __restrict__ Q, const float* __restrict__ P) {
    const float* M = (blockIdx.x < RR) ? Q : P;
    int i = blockIdx.x & (RR - 1);
    __shared__ float col[DD];
    __shared__ double red[RR];
    for (int d = threadIdx.x; d < DD; d += RR) col[d] = M[(size_t)d * RR + i];
    __syncthreads();
    int j = threadIdx.x;
    float s1 = 0.0f, s2 = 0.0f;
    for (int d = 0; d < DD / 2; d++)
        s1 = fmaf(col[d], M[(size_t)d * RR + j], s1);
    for (int d = DD / 2; d < DD; d++)
        s2 = fmaf(col[d], M[(size_t)d * RR + j], s2);
    float G = s1 + s2;
    double r = (double)G - (j == i ? 1.0 : 0.0);
    red[j] = r * r;
    __syncthreads();
    for (int st = RR / 2; st > 0; st >>= 1) {
        if (j < st) red[j] += red[j + st];
        __syncthreads();
    }
    if (j == 0) atomicAdd(&g_ortho, red[0]);
}

// ======== shared fp16 GEMM mainloop macro pieces (A[m][k], B[k2][n]) ========
// warp tile 64x32: wm = wid&1 (m), wn = wid>>1 (n), fragments per PTX m16n8k16.

// ---------------- router (fp16 mma + fused softmax) ----------------
__global__ __launch_bounds__(256) void router_kernel(
    const float* __restrict__ gamma, const float* __restrict__ masks,
    const float* __restrict__ bias) {
    extern __shared__ char smc[];
    __half* Ah = (__half*)smc;                            // [2][128][40]
    uint32_t* Bs2 = (uint32_t*)(smc + 2 * ASH_BUF * 2);   // [2][16][136]
    float* zs = (float*)smc;                              // [128][129] alias
    float* gmv = (float*)(smc + 128 * RZS * 4);           // [8][129]
    __shared__ float entS[128];

    int tid = threadIdx.x;
    int lane = tid & 31, wid = tid >> 5;
    int wm = wid & 1, wn = wid >> 1;
    int g = lane >> 2, t = lane & 3;
    int tok0 = blockIdx.x * 128;
    const __half* arow = g_xth + (size_t)tok0 * DD;

    if (tid < 128) {
        float mv[EE];
        float mx = -1e30f;
        #pragma unroll
        for (int e = 0; e < EE; e++) { mv[e] = masks[e * RR + tid]; mx = fmaxf(mx, mv[e]); }
        float ss = 0.0f;
        #pragma unroll
        for (int e = 0; e < EE; e++) { mv[e] = expf(mv[e] - mx); ss += mv[e]; }
        float gsc = gamma[tid] / ss;
        #pragma unroll
        for (int e = 0; e < EE; e++) gmv[e * RZS + tid] = mv[e] * gsc;
    }

    float acc[16][4];
    #pragma unroll
    for (int i = 0; i < 16; i++)
        #pragma unroll
        for (int j = 0; j < 4; j++) acc[i][j] = 0.0f;

    #pragma unroll
    for (int l = 0; l < 2; l++) {
        int lin = tid + 256 * l;
        int row = lin >> 2, ch = (lin & 3) * 8;
        cp_async16(Ah + row * ASH_STRIDE + ch, arow + (size_t)row * DD + ch);
        int kk = lin >> 5, c4 = (lin & 31) * 4;
        cp_async16(Bs2 + kk * BS2_STRIDE + c4, g_qt2 + (size_t)kk * RR + c4);
    }
    CP_COMMIT();

    const int NIT = DD / 32;
    for (int it = 0; it < NIT; it++) {
        int buf = it & 1;
        if (it + 1 < NIT) {
            int kb = (it + 1) * 32;
            int nbuf = buf ^ 1;
            #pragma unroll
            for (int l = 0; l < 2; l++) {
                int lin = tid + 256 * l;
                int row = lin >> 2, ch = (lin & 3) * 8;
                cp_async16(Ah + nbuf * ASH_BUF + row * ASH_STRIDE + ch,
                           arow + (size_t)row * DD + kb + ch);
                int kk = lin >> 5, c4 = (lin & 31) * 4;
                cp_async16(Bs2 + nbuf * BS2_BUF + kk * BS2_STRIDE + c4,
                           g_qt2 + (size_t)(kb / 2 + kk) * RR + c4);
            }
            CP_COMMIT();
            CP_WAIT1();
        } else {
            CP_WAIT0();
        }
        __syncthreads();
        const __half* Ab = Ah + buf * ASH_BUF;
        const uint32_t* Bb = Bs2 + buf * BS2_BUF;
        #pragma unroll
        for (int ks = 0; ks < 2; ks++) {
            int k0 = ks * 16, k20 = ks * 8;
            uint32_t bfr[4][2];
            #pragma unroll
            for (int nf = 0; nf < 4; nf++) {
                int n0 = wn * 32 + nf * 8;
                bfr[nf][0] = Bb[(k20 + t) * BS2_STRIDE + n0 + g];
                bfr[nf][1] = Bb[(k20 + 4 + t) * BS2_STRIDE + n0 + g];
            }
            #pragma unroll
            for (int mf = 0; mf < 4; mf++) {
                int m0 = wm * 64 + mf * 16;
                uint32_t a0 = *(const uint32_t*)(Ab + (m0 + g) * ASH_STRIDE + k0 + 2 * t);
                uint32_t a1 = *(const uint32_t*)(Ab + (m0 + g + 8) * ASH_STRIDE + k0 + 2 * t);
                uint32_t a2 = *(const uint32_t*)(Ab + (m0 + g) * ASH_STRIDE + k0 + 8 + 2 * t);
                uint32_t a3 = *(const uint32_t*)(Ab + (m0 + g + 8) * ASH_STRIDE + k0 + 8 + 2 * t);
                #pragma unroll
                for (int nf = 0; nf < 4; nf++)
                    mma_f16(acc[mf * 4 + nf], a0, a1, a2, a3, bfr[nf][0], bfr[nf][1]);
            }
        }
        __syncthreads();
    }
    #pragma unroll
    for (int mf = 0; mf < 4; mf++) {
        #pragma unroll
        for (int nf = 0; nf < 4; nf++) {
            float* c = acc[mf * 4 + nf];
            int cl = wn * 32 + nf * 8 + 2 * t;
            #pragma unroll
            for (int h = 0; h < 2; h++) {
                int r = wm * 64 + mf * 16 + g + h * 8;
                zs[r * RZS + cl]     = c[h * 2] * c[h * 2];
                zs[r * RZS + cl + 1] = c[h * 2 + 1] * c[h * 2 + 1];
            }
        }
    }
    __syncthreads();

    if (tid < 128) {
        float s = 0.0f;
        float lg[EE];
        #pragma unroll
        for (int e = 0; e < EE; e++) lg[e] = 0.0f;
        #pragma unroll 4
        for (int r = 0; r < RR; r++) {
            float zq = zs[tid * RZS + r];
            s += zq;
            #pragma unroll
            for (int e = 0; e < EE; e++) lg[e] = fmaf(zq, gmv[e * RZS + r], lg[e]);
        }
        float sinv = 1.0f / (s + 1e-6f);
        float mx = -1e30f;
        #pragma unroll
        for (int e = 0; e < EE; e++) { lg[e] = lg[e] * sinv + bias[e]; mx = fmaxf(mx, lg[e]); }
        float ss = 0.0f;
        #pragma unroll
        for (int e = 0; e < EE; e++) { lg[e] = expf(lg[e] - mx); ss += lg[e]; }
        float inv = 1.0f / ss;
        float hent = 0.0f;
        #pragma unroll
        for (int e = 0; e < EE; e++) {
            float p = lg[e] * inv;
            hent -= p * logf(fmaxf(p, 1e-9f));
            g_probs[(size_t)(tok0 + tid) * EE + e] = p;
        }
        entS[tid] = hent;
    }
    __syncthreads();
    for (int st = 64; st > 0; st >>= 1) {
        if (tid < st && tid + st < 128) entS[tid] += entS[tid + st];
        __syncthreads();
    }
    if (tid == 0) atomicAdd(&g_ent, (double)entS[0]);
}

// ---------------- down GEMM (fp16 mma, cp.async) ----------------
__global__ __launch_bounds__(256, 2) void down_kernel() {
    extern __shared__ char smc[];
    __half* Ah = (__half*)smc;
    uint32_t* Bs2 = (uint32_t*)(smc + 2 * ASH_BUF * 2);
    __shared__ float sh_probs[128][EE];
    int tid = threadIdx.x;
    int lane = tid & 31, wid = tid >> 5;
    int wm = wid & 1, wn = wid >> 1;
    int g = lane >> 2, t = lane & 3;
    int mb = blockIdx.y, nb = blockIdx.x;
    const __half* arow = g_xth + (size_t)mb * 128 * DD;

    {
        int r = tid >> 1, c4 = (tid & 1) * 4;
        *(float4*)&sh_probs[r][c4] =
            *(const float4*)(g_probs + (size_t)(mb * 128 + r) * EE + c4);
    }

    float acc[16][4];
    #pragma unroll
    for (int i = 0; i < 16; i++)
        #pragma unroll
        for (int j = 0; j < 4; j++) acc[i][j] = 0.0f;

    #pragma unroll
    for (int l = 0; l < 2; l++) {
        int lin = tid + 256 * l;
        int row = lin >> 2, ch = (lin & 3) * 8;
        cp_async16(Ah + row * ASH_STRIDE + ch, arow + (size_t)row * DD + ch);
        int kk = lin >> 5, c4 = (lin & 31) * 4;
        cp_async16(Bs2 + kk * BS2_STRIDE + c4,
                   g_wdt2 + (size_t)kk * N1 + nb * 128 + c4);
    }
    CP_COMMIT();

    const int NIT = DD / 32;
    for (int it = 0; it < NIT; it++) {
        int buf = it & 1;
        if (it + 1 < NIT) {
            int kb = (it + 1) * 32;
            int nbuf = buf ^ 1;
            #pragma unroll
            for (int l = 0; l < 2; l++) {
                int lin = tid + 256 * l;
                int row = lin >> 2, ch = (lin & 3) * 8;
                cp_async16(Ah + nbuf * ASH_BUF + row * ASH_STRIDE + ch,
                           arow + (size_t)row * DD + kb + ch);
                int kk = lin >> 5, c4 = (lin & 31) * 4;
                cp_async16(Bs2 + nbuf * BS2_BUF + kk * BS2_STRIDE + c4,
                           g_wdt2 + (size_t)(kb / 2 + kk) * N1 + nb * 128 + c4);
            }
            CP_COMMIT();
            CP_WAIT1();
        } else {
            CP_WAIT0();
        }
        __syncthreads();
        const __half* Ab = Ah + buf * ASH_BUF;
        const uint32_t* Bb = Bs2 + buf * BS2_BUF;
        #pragma unroll
        for (int ks = 0; ks < 2; ks++) {
            int k0 = ks * 16, k20 = ks * 8;
            uint32_t bfr[4][2];
            #pragma unroll
            for (int nf = 0; nf < 4; nf++) {
                int n0 = wn * 32 + nf * 8;
                bfr[nf][0] = Bb[(k20 + t) * BS2_STRIDE + n0 + g];
                bfr[nf][1] = Bb[(k20 + 4 + t) * BS2_STRIDE + n0 + g];
            }
            #pragma unroll
            for (int mf = 0; mf < 4; mf++) {
                int m0 = wm * 64 + mf * 16;
                uint32_t a0 = *(const uint32_t*)(Ab + (m0 + g) * ASH_STRIDE + k0 + 2 * t);
                uint32_t a1 = *(const uint32_t*)(Ab + (m0 + g + 8) * ASH_STRIDE + k0 + 2 * t);
                uint32_t a2 = *(const uint32_t*)(Ab + (m0 + g) * ASH_STRIDE + k0 + 8 + 2 * t);
                uint32_t a3 = *(const uint32_t*)(Ab + (m0 + g + 8) * ASH_STRIDE + k0 + 8 + 2 * t);
                #pragma unroll
                for (int nf = 0; nf < 4; nf++)
                    mma_f16(acc[mf * 4 + nf], a0, a1, a2, a3, bfr[nf][0], bfr[nf][1]);
            }
        }
        __syncthreads();
    }
    #pragma unroll
    for (int mf = 0; mf < 4; mf++) {
        #pragma unroll
        for (int nf = 0; nf < 4; nf++) {
            float* c = acc[mf * 4 + nf];
            int cl = wn * 32 + nf * 8 + 2 * t;
            int ncol = nb * 128 + cl;
            int e = ncol / CC;
            #pragma unroll
            for (int h = 0; h < 2; h++) {
                int r = wm * 64 + mf * 16 + g + h * 8;
                float p = sh_probs[r][e];
                float v0 = c[h * 2], v1 = c[h * 2 + 1];
                float g0 = 0.5f * v0 * (1.0f + erff(v0 * 0.70710678118654752f)) * p;
                float g1 = 0.5f * v1 * (1.0f + erff(v1 * 0.70710678118654752f)) * p;
                __half2 hv = __floats2half2_rn(g0, g1);
                *(uint32_t*)(g_midh + (size_t)(mb * 128 + r) * N1 + ncol) = *(uint32_t*)&hv;
            }
        }
    }
}

// ---------------- up GEMM (fp16 mma, cp.async) ----------------
__global__ __launch_bounds__(256, 2) void up_kernel(const float* __restrict__ x,
                                                    const float* __restrict__ alphap,
                                                    float* __restrict__ out) {
    extern __shared__ char smc[];
    __half* Ah = (__half*)smc;
    uint32_t* Bs2 = (uint32_t*)(smc + 2 * ASH_BUF * 2);
    int tid = threadIdx.x;
    int lane = tid & 31, wid = tid >> 5;
    int wm = wid & 1, wn = wid >> 1;
    int g = lane >> 2, t = lane & 3;
    int mb = blockIdx.y, nb = blockIdx.x;
    const __half* amid = g_midh + (size_t)mb * 128 * N1;

    float acc[16][4];
    #pragma unroll
    for (int i = 0; i < 16; i++)
        #pragma unroll
        for (int j = 0; j < 4; j++) acc[i][j] = 0.0f;

    #pragma unroll
    for (int l = 0; l < 2; l++) {
        int lin = tid + 256 * l;
        int row = lin >> 2, ch = (lin & 3) * 8;
        cp_async16(Ah + row * ASH_STRIDE + ch, amid + (size_t)row * N1 + ch);
        int kk = lin >> 5, c4 = (lin & 31) * 4;
        cp_async16(Bs2 + kk * BS2_STRIDE + c4,
                   g_wut2 + (size_t)kk * DD + nb * 128 + c4);
    }
    CP_COMMIT();

    const int NIT = N1 / 32;
    for (int it = 0; it < NIT; it++) {
        int buf = it & 1;
        if (it + 1 < NIT) {
            int kb = (it + 1) * 32;
            int nbuf = buf ^ 1;
            #pragma unroll
            for (int l = 0; l < 2; l++) {
                int lin = tid + 256 * l;
                int row = lin >> 2, ch = (lin & 3) * 8;
                cp_async16(Ah + nbuf * ASH_BUF + row * ASH_STRIDE + ch,
                           amid + (size_t)row * N1 + kb + ch);
                int kk = lin >> 5, c4 = (lin & 31) * 4;
                cp_async16(Bs2 + nbuf * BS2_BUF + kk * BS2_STRIDE + c4,
                           g_wut2 + (size_t)(kb / 2 + kk) * DD + nb * 128 + c4);
            }
            CP_COMMIT();
            CP_WAIT1();
        } else {
            CP_WAIT0();
        }
        __syncthreads();
        const __half* Ab = Ah + buf * ASH_BUF;
        const uint32_t* Bb = Bs2 + buf * BS2_BUF;
        #pragma unroll
        for (int ks = 0; ks < 2; ks++) {
            int k0 = ks * 16, k20 = ks * 8;
            uint32_t bfr[4][2];
            #pragma unroll
            for (int nf = 0; nf < 4; nf++) {
                int n0 = wn * 32 + nf * 8;
                bfr[nf][0] = Bb[(k20 + t) * BS2_STRIDE + n0 + g];
                bfr[nf][1] = Bb[(k20 + 4 + t) * BS2_STRIDE + n0 + g];
            }
            #pragma unroll
            for (int mf = 0; mf < 4; mf++) {
                int m0 = wm * 64 + mf * 16;
                uint32_t a0 = *(const uint32_t*)(Ab + (m0 + g) * ASH_STRIDE + k0 + 2 * t);
                uint32_t a1 = *(const uint32_t*)(Ab + (m0 + g + 8) * ASH_STRIDE + k0 + 2 * t);
                uint32_t a2 = *(const uint32_t*)(Ab + (m0 + g) * ASH_STRIDE + k0 + 8 + 2 * t);
                uint32_t a3 = *(const uint32_t*)(Ab + (m0 + g + 8) * ASH_STRIDE + k0 + 8 + 2 * t);
                #pragma unroll
                for (int nf = 0; nf < 4; nf++)
                    mma_f16(acc[mf * 4 + nf], a0, a1, a2, a3, bfr[nf][0], bfr[nf][1]);
            }
        }
        __syncthreads();
    }
    float alpha = *alphap;
    #pragma unroll
    for (int mf = 0; mf < 4; mf++) {
        #pragma unroll
        for (int nf = 0; nf < 4; nf++) {
            float* c = acc[mf * 4 + nf];
            int cl = wn * 32 + nf * 8 + 2 * t;
            int ncol = nb * 128 + cl;
            #pragma unroll
            for (int h = 0; h < 2; h++) {
                int r = wm * 64 + mf * 16 + g + h * 8;
                int gi = mb * 128 + r;
                int b = gi >> 10;
                int tt = (gi & 1023) + 1;
                size_t ro = ((size_t)b * TT + tt) * DD + ncol;
                float2 hx = *(const float2*)(x + ro);
                *(float2*)(out + ro) = make_float2(fmaf(alpha, c[h * 2], hx.x),
                                                   fmaf(alpha, c[h * 2 + 1], hx.y));
            }
        }
    }
}

// ---------------- launch ----------------
extern "C" void kernel_launch(void* const* d_in, const int* in_sizes, int n_in,
                              void* d_out, int out_size) {
    const float* x     = (const float*)d_in[0];
    const float* Q     = (const float*)d_in[1];
    const float* P     = (const float*)d_in[2];
    const float* gamma = (const float*)d_in[3];
    const float* masks = (const float*)d_in[4];
    const float* bias  = (const float*)d_in[5];
    const float* Wd    = (const float*)d_in[6];
    const float* Wu    = (const float*)d_in[7];
    const float* alpha = (const float*)d_in[8];
    float* out = (float*)d_out;

    cudaFuncSetAttribute(router_kernel,
                         cudaFuncAttributeMaxDynamicSharedMemorySize, ROUTER_DYN_SMEM);
    cudaFuncSetAttribute(down_kernel,
                         cudaFuncAttributeMaxDynamicSharedMemorySize, GEMM_DYN_SMEM);
    cudaFuncSetAttribute(up_kernel,
                         cudaFuncAttributeMaxDynamicSharedMemorySize, GEMM_DYN_SMEM);

    init_kernel<<<(BB * DD / 4 + 2 + 255) / 256, 256>>>(x, out);
    xconvert_kernel<<<(NTOK * DD / 4 + 255) / 256, 256>>>(x);
    wconvert_kernel<<<2048, 256>>>(Wd, Wu, Q);
    ortho_kernel<<<2 * RR, RR>>>(Q, P);
    router_kernel<<<NTOK / 128, 256, ROUTER_DYN_SMEM>>>(gamma, masks, bias);
    down_kernel<<<dim3(N1 / 128, NTOK / 128), 256, GEMM_DYN_SMEM>>>();
    up_kernel<<<dim3(DD / 128, NTOK / 128), 256, GEMM_DYN_SMEM>>>(x, alpha, out);
    finalize_kernel<<<1, 32>>>(out);
}